// round 2
// baseline (speedup 1.0000x reference)
#include <cuda_runtime.h>
#include <cuda_bf16.h>
#include <math.h>

#define BATCH 8
#define SEQ   1024
#define CDIM  768
#define NH    12
#define HD    64
#define N3    (3*CDIM)

// Scratch (no allocations allowed): Q/K/V in [B,H,T,hd] layout, attn out in [B,T,C]
__device__ float g_q[BATCH*NH*SEQ*HD];
__device__ float g_k[BATCH*NH*SEQ*HD];
__device__ float g_v[BATCH*NH*SEQ*HD];
__device__ float g_att[BATCH*SEQ*CDIM];

// ---------------------------------------------------------------------------
// GEMM: C[M,N] = A[M,K] @ W[K,N] + bias[N]
// BM=BN=64, BK=16, 256 threads, 4x4 microtile per thread.
// MODE 0: A = g_att (read internally), plain store to Cout (proj).
// MODE 1: A = Ain argument (x), scatter QKV into g_q/g_k/g_v.
// NOTE: __device__ globals must NOT be passed as kernel args from host code
// (host symbol shadow address + GB300 ATS = silent zeros). Access them only
// from device code.
// ---------------------------------------------------------------------------
template<int MODE, int K, int N>
__global__ void gemm_kernel(const float* __restrict__ Ain,
                            const float* __restrict__ W,
                            const float* __restrict__ bias,
                            float* __restrict__ Cout)
{
    const float* A = (MODE == 0) ? (const float*)g_att : Ain;

    __shared__ float As[16][64];   // [k][m]
    __shared__ float Bs[16][64];   // [k][n]

    const int tid = threadIdx.x;
    const int bm = blockIdx.y * 64;
    const int bn = blockIdx.x * 64;

    const int tx = tid & 15;       // 0..15 -> n
    const int ty = tid >> 4;       // 0..15 -> m

    // load mapping
    const int arow = tid >> 2;           // 0..63
    const int acol = (tid & 3) * 4;      // 0,4,8,12
    const int brow = tid >> 4;           // 0..15
    const int bcol = (tid & 15) * 4;     // 0..60

    float acc[4][4];
    #pragma unroll
    for (int i = 0; i < 4; i++)
        #pragma unroll
        for (int j = 0; j < 4; j++) acc[i][j] = 0.f;

    for (int k0 = 0; k0 < K; k0 += 16) {
        float4 av = *(const float4*)&A[(size_t)(bm + arow) * K + k0 + acol];
        As[acol + 0][arow] = av.x;
        As[acol + 1][arow] = av.y;
        As[acol + 2][arow] = av.z;
        As[acol + 3][arow] = av.w;
        float4 bv = *(const float4*)&W[(size_t)(k0 + brow) * N + bn + bcol];
        *(float4*)&Bs[brow][bcol] = bv;
        __syncthreads();

        #pragma unroll
        for (int kk = 0; kk < 16; kk++) {
            float a0 = As[kk][ty*4+0];
            float a1 = As[kk][ty*4+1];
            float a2 = As[kk][ty*4+2];
            float a3 = As[kk][ty*4+3];
            float4 b = *(const float4*)&Bs[kk][tx*4];
            acc[0][0] += a0*b.x; acc[0][1] += a0*b.y; acc[0][2] += a0*b.z; acc[0][3] += a0*b.w;
            acc[1][0] += a1*b.x; acc[1][1] += a1*b.y; acc[1][2] += a1*b.z; acc[1][3] += a1*b.w;
            acc[2][0] += a2*b.x; acc[2][1] += a2*b.y; acc[2][2] += a2*b.z; acc[2][3] += a2*b.w;
            acc[3][0] += a3*b.x; acc[3][1] += a3*b.y; acc[3][2] += a3*b.z; acc[3][3] += a3*b.w;
        }
        __syncthreads();
    }

    #pragma unroll
    for (int i = 0; i < 4; i++) {
        int m = bm + ty*4 + i;
        #pragma unroll
        for (int j = 0; j < 4; j++) {
            int n = bn + tx*4 + j;
            float v = acc[i][j] + bias[n];
            if (MODE == 0) {
                Cout[(size_t)m * N + n] = v;
            } else {
                // scatter into Q/K/V head-major [B,H,T,hd]
                int which = n / CDIM;
                int c = n - which * CDIM;
                int h = c >> 6;
                int d = c & 63;
                int b = m >> 10;
                int t = m & 1023;
                size_t idx = (((size_t)(b * NH + h) * SEQ) + t) * HD + d;
                if (which == 0) g_q[idx] = v;
                else if (which == 1) g_k[idx] = v;
                else g_v[idx] = v;
            }
        }
    }
}

// ---------------------------------------------------------------------------
// Attention: per (b, h, 16-query block). Scores for the full 1024-key row kept
// in dynamic smem, warp-owned-row softmax, then P@V with 64-key V tiles.
// 256 threads. Dyn smem = (16*1024 + 16*64 + 64*65) floats = 86272 B.
// ---------------------------------------------------------------------------
#define BQ 16
#define KT 64
#define KVPAD 65

__global__ void attn_kernel(const int* __restrict__ mask)
{
    extern __shared__ float sm[];
    float* S   = sm;                   // [BQ][1024]
    float* Qs  = sm + BQ * SEQ;        // [BQ][64]
    float* KVs = Qs + BQ * HD;         // [64][65]

    const int b  = blockIdx.z;
    const int h  = blockIdx.y;
    const int qb = blockIdx.x;
    const int q0 = qb * BQ;

    const float* Qp = g_q + ((size_t)(b * NH + h) * SEQ) * HD;
    const float* Kp = g_k + ((size_t)(b * NH + h) * SEQ) * HD;
    const float* Vp = g_v + ((size_t)(b * NH + h) * SEQ) * HD;

    const int tid = threadIdx.x;
    const int ty = tid >> 5;   // warp 0..7
    const int tx = tid & 31;   // lane

    // load Q tile (16x64), one float4 per thread
    {
        int r = tid >> 4;
        int c = (tid & 15) * 4;
        *(float4*)&Qs[r * HD + c] = *(const float4*)&Qp[(size_t)(q0 + r) * HD + c];
    }

    const float scale = 0.125f;  // 1/sqrt(64)

    // ---- scores ----
    for (int kt = 0; kt < SEQ / KT; kt++) {
        // load K tile 64x64 -> KVs[64][65]
        {
            int g = tid >> 4;             // 0..15
            int c = (tid & 15) * 4;
            #pragma unroll
            for (int i = 0; i < 4; i++) {
                int r = g * 4 + i;
                float4 kv = *(const float4*)&Kp[(size_t)(kt * KT + r) * HD + c];
                KVs[r * KVPAD + c + 0] = kv.x;
                KVs[r * KVPAD + c + 1] = kv.y;
                KVs[r * KVPAD + c + 2] = kv.z;
                KVs[r * KVPAD + c + 3] = kv.w;
            }
        }
        __syncthreads();

        // each thread: q in {2ty, 2ty+1}, k in {tx, tx+32}
        float s00 = 0.f, s01 = 0.f, s10 = 0.f, s11 = 0.f;
        const float* q0p = &Qs[(ty * 2 + 0) * HD];
        const float* q1p = &Qs[(ty * 2 + 1) * HD];
        const float* k0p = &KVs[tx * KVPAD];
        const float* k1p = &KVs[(tx + 32) * KVPAD];
        #pragma unroll
        for (int d = 0; d < HD; d++) {
            float qa = q0p[d], qb2 = q1p[d];
            float ka = k0p[d], kb = k1p[d];
            s00 += qa * ka; s01 += qa * kb;
            s10 += qb2 * ka; s11 += qb2 * kb;
        }
        int kg0 = kt * KT + tx;
        int kg1 = kt * KT + tx + 32;
        int m0 = mask[b * SEQ + kg0];
        int m1 = mask[b * SEQ + kg1];
        S[(ty*2+0) * SEQ + kg0] = (m0 == 0) ? -1e30f : s00 * scale;
        S[(ty*2+0) * SEQ + kg1] = (m1 == 0) ? -1e30f : s01 * scale;
        S[(ty*2+1) * SEQ + kg0] = (m0 == 0) ? -1e30f : s10 * scale;
        S[(ty*2+1) * SEQ + kg1] = (m1 == 0) ? -1e30f : s11 * scale;
        __syncthreads();
    }

    // ---- softmax (each warp owns rows 2ty, 2ty+1; inv-sum folded into output) ----
    float inv[2];
    #pragma unroll
    for (int iq = 0; iq < 2; iq++) {
        float* row = &S[(ty * 2 + iq) * SEQ];
        float mx = -1e30f;
        for (int j = tx; j < SEQ; j += 32) mx = fmaxf(mx, row[j]);
        #pragma unroll
        for (int o = 16; o > 0; o >>= 1) mx = fmaxf(mx, __shfl_xor_sync(0xffffffff, mx, o));
        float sum = 0.f;
        for (int j = tx; j < SEQ; j += 32) {
            float e = __expf(row[j] - mx);
            row[j] = e;
            sum += e;
        }
        #pragma unroll
        for (int o = 16; o > 0; o >>= 1) sum += __shfl_xor_sync(0xffffffff, sum, o);
        inv[iq] = 1.f / sum;
    }

    // ---- P @ V ----
    float o00 = 0.f, o01 = 0.f, o10 = 0.f, o11 = 0.f;  // q in {2ty,2ty+1}, d in {tx, tx+32}
    for (int kt = 0; kt < SEQ / KT; kt++) {
        __syncthreads();
        {
            int g = tid >> 4;
            int c = (tid & 15) * 4;
            #pragma unroll
            for (int i = 0; i < 4; i++) {
                int r = g * 4 + i;
                float4 vv = *(const float4*)&Vp[(size_t)(kt * KT + r) * HD + c];
                KVs[r * KVPAD + c + 0] = vv.x;
                KVs[r * KVPAD + c + 1] = vv.y;
                KVs[r * KVPAD + c + 2] = vv.z;
                KVs[r * KVPAD + c + 3] = vv.w;
            }
        }
        __syncthreads();

        const float* p0 = &S[(ty*2+0) * SEQ + kt * KT];
        const float* p1 = &S[(ty*2+1) * SEQ + kt * KT];
        #pragma unroll
        for (int kk = 0; kk < KT; kk++) {
            float pa = p0[kk], pb = p1[kk];
            float va = KVs[kk * KVPAD + tx];
            float vb = KVs[kk * KVPAD + tx + 32];
            o00 += pa * va; o01 += pa * vb;
            o10 += pb * va; o11 += pb * vb;
        }
    }

    // store to g_att [B,T,C] with C index = h*64 + d
    {
        size_t base0 = ((size_t)(b * SEQ + q0 + ty*2 + 0)) * CDIM + h * HD;
        size_t base1 = ((size_t)(b * SEQ + q0 + ty*2 + 1)) * CDIM + h * HD;
        g_att[base0 + tx]      = o00 * inv[0];
        g_att[base0 + tx + 32] = o01 * inv[0];
        g_att[base1 + tx]      = o10 * inv[1];
        g_att[base1 + tx + 32] = o11 * inv[1];
    }
}

// ---------------------------------------------------------------------------
extern "C" void kernel_launch(void* const* d_in, const int* in_sizes, int n_in,
                              void* d_out, int out_size)
{
    const float* x      = (const float*)d_in[0];
    const int*   amask  = (const int*)  d_in[1];
    const float* W_attn = (const float*)d_in[2];
    const float* b_attn = (const float*)d_in[3];
    const float* W_proj = (const float*)d_in[4];
    const float* b_proj = (const float*)d_in[5];
    float* out = (float*)d_out;

    // 1) QKV GEMM with scatter into g_q/g_k/g_v
    {
        dim3 grid(N3 / 64, (BATCH * SEQ) / 64);
        gemm_kernel<1, CDIM, N3><<<grid, 256>>>(x, W_attn, b_attn, nullptr);
    }

    // 2) attention
    {
        int smem = (BQ * SEQ + BQ * HD + KT * KVPAD) * (int)sizeof(float);
        cudaFuncSetAttribute(attn_kernel, cudaFuncAttributeMaxDynamicSharedMemorySize, smem);
        dim3 grid(SEQ / BQ, NH, BATCH);
        attn_kernel<<<grid, 256, smem>>>(amask);
    }

    // 3) proj GEMM (A = g_att read inside the kernel, NOT passed from host)
    {
        dim3 grid(CDIM / 64, (BATCH * SEQ) / 64);
        gemm_kernel<0, CDIM, CDIM><<<grid, 256>>>(nullptr, W_proj, b_proj, out);
    }
}

// round 3
// speedup vs baseline: 1.5005x; 1.5005x over previous
#include <cuda_runtime.h>
#include <cuda_bf16.h>
#include <math.h>
#include <stdint.h>

#define BATCH 8
#define SEQ   1024
#define CDIM  768
#define NH    12
#define HD    64
#define N3    (3*CDIM)

// Scratch (no allocations allowed): Q/K/V in [B,H,T,hd] layout, attn out in [B,T,C]
__device__ float g_q[BATCH*NH*SEQ*HD];
__device__ float g_k[BATCH*NH*SEQ*HD];
__device__ float g_v[BATCH*NH*SEQ*HD];
__device__ float g_att[BATCH*SEQ*CDIM];

// ---------------------------------------------------------------------------
// tf32 helpers
// ---------------------------------------------------------------------------
__device__ __forceinline__ uint32_t f2tf32(float x) {
    uint32_t u;
    asm("cvt.rna.tf32.f32 %0, %1;" : "=r"(u) : "f"(x));
    return u;
}

__device__ __forceinline__ void mma_tf32(float* c, const uint32_t* a, const uint32_t* b) {
    asm volatile(
        "mma.sync.aligned.m16n8k8.row.col.f32.tf32.tf32.f32 "
        "{%0,%1,%2,%3}, {%4,%5,%6,%7}, {%8,%9}, {%0,%1,%2,%3};"
        : "+f"(c[0]), "+f"(c[1]), "+f"(c[2]), "+f"(c[3])
        : "r"(a[0]), "r"(a[1]), "r"(a[2]), "r"(a[3]), "r"(b[0]), "r"(b[1]));
}

// ---------------------------------------------------------------------------
// Tensor-core GEMM: C[M,N] = A[M,K] @ W[K,N] + bias[N]   (tf32, fp32 accum)
// BM=128, BN=128, BK=32, 256 threads (8 warps, 2x4 warp grid, 64x32 per warp).
// MODE 0: A = g_att (device global, read internally), plain store to Cout.
// MODE 1: A = Ain (x), scatter QKV into g_q/g_k/g_v head-major.
// ---------------------------------------------------------------------------
#define LDA 36    // A smem row stride (floats): 32 + 4 pad -> conflict-free frags
#define LDB 136   // B smem row stride (floats): 128 + 8 pad -> conflict-free frags

template<int MODE, int K, int N>
__global__ __launch_bounds__(256)
void gemm_tc(const float* __restrict__ Ain,
             const float* __restrict__ W,
             const float* __restrict__ bias,
             float* __restrict__ Cout)
{
    const float* A = (MODE == 0) ? (const float*)g_att : Ain;

    __shared__ uint32_t As[128 * LDA];  // [m][k]
    __shared__ uint32_t Bs[32 * LDB];   // [k][n]

    const int tid  = threadIdx.x;
    const int bm   = blockIdx.y * 128;
    const int bn   = blockIdx.x * 128;
    const int warp = tid >> 5;
    const int lane = tid & 31;
    const int wm   = warp & 1;          // 0..1 -> 64-row half
    const int wn   = warp >> 1;         // 0..3 -> 32-col slice
    const int g    = lane >> 2;         // 0..7
    const int t4   = lane & 3;          // 0..3

    float acc[4][4][4];
    #pragma unroll
    for (int mt = 0; mt < 4; mt++)
        #pragma unroll
        for (int nt = 0; nt < 4; nt++)
            #pragma unroll
            for (int i = 0; i < 4; i++) acc[mt][nt][i] = 0.f;

    for (int k0 = 0; k0 < K; k0 += 32) {
        // ---- load A tile 128x32 -> As[m][k] (tf32-converted) ----
        #pragma unroll
        for (int i = 0; i < 4; i++) {
            int linear = tid + i * 256;          // 0..1023
            int row = linear >> 3;               // 0..127
            int c4  = (linear & 7) * 4;          // 0..28
            float4 v = *(const float4*)&A[(size_t)(bm + row) * K + k0 + c4];
            uint4 u;
            u.x = f2tf32(v.x); u.y = f2tf32(v.y); u.z = f2tf32(v.z); u.w = f2tf32(v.w);
            *(uint4*)&As[row * LDA + c4] = u;
        }
        // ---- load B tile 32x128 -> Bs[k][n] (tf32-converted) ----
        #pragma unroll
        for (int i = 0; i < 4; i++) {
            int linear = tid + i * 256;
            int row = linear >> 5;               // 0..31
            int c4  = (linear & 31) * 4;         // 0..124
            float4 v = *(const float4*)&W[(size_t)(k0 + row) * N + bn + c4];
            uint4 u;
            u.x = f2tf32(v.x); u.y = f2tf32(v.y); u.z = f2tf32(v.z); u.w = f2tf32(v.w);
            *(uint4*)&Bs[row * LDB + c4] = u;
        }
        __syncthreads();

        #pragma unroll
        for (int ks = 0; ks < 4; ks++) {
            const int kk = ks * 8;
            uint32_t a[4][4], b[4][2];
            #pragma unroll
            for (int mt = 0; mt < 4; mt++) {
                int m0 = wm * 64 + mt * 16 + g;
                a[mt][0] = As[(m0)     * LDA + kk + t4];
                a[mt][1] = As[(m0 + 8) * LDA + kk + t4];
                a[mt][2] = As[(m0)     * LDA + kk + t4 + 4];
                a[mt][3] = As[(m0 + 8) * LDA + kk + t4 + 4];
            }
            #pragma unroll
            for (int nt = 0; nt < 4; nt++) {
                int n0 = wn * 32 + nt * 8 + g;
                b[nt][0] = Bs[(kk + t4)     * LDB + n0];
                b[nt][1] = Bs[(kk + t4 + 4) * LDB + n0];
            }
            #pragma unroll
            for (int mt = 0; mt < 4; mt++)
                #pragma unroll
                for (int nt = 0; nt < 4; nt++)
                    mma_tf32(acc[mt][nt], a[mt], b[nt]);
        }
        __syncthreads();
    }

    // ---- epilogue ----
    #pragma unroll
    for (int mt = 0; mt < 4; mt++) {
        #pragma unroll
        for (int nt = 0; nt < 4; nt++) {
            #pragma unroll
            for (int i = 0; i < 4; i++) {
                int m = bm + wm * 64 + mt * 16 + g + (i >> 1) * 8;
                int n = bn + wn * 32 + nt * 8 + 2 * t4 + (i & 1);
                float v = acc[mt][nt][i] + bias[n];
                if (MODE == 0) {
                    Cout[(size_t)m * N + n] = v;
                } else {
                    int which = n / CDIM;
                    int c = n - which * CDIM;
                    int h = c >> 6;
                    int d = c & 63;
                    int b2 = m >> 10;
                    int t = m & 1023;
                    size_t idx = (((size_t)(b2 * NH + h) * SEQ) + t) * HD + d;
                    if (which == 0) g_q[idx] = v;
                    else if (which == 1) g_k[idx] = v;
                    else g_v[idx] = v;
                }
            }
        }
    }
}

// ---------------------------------------------------------------------------
// Attention: per (b, h, 16-query block). Scores for the full 1024-key row kept
// in dynamic smem, warp-owned-row softmax, then P@V with 64-key V tiles.
// 256 threads. Dyn smem = (16*1024 + 16*64 + 64*65) floats = 86272 B.
// ---------------------------------------------------------------------------
#define BQ 16
#define KT 64
#define KVPAD 65

__global__ void attn_kernel(const int* __restrict__ mask)
{
    extern __shared__ float sm[];
    float* S   = sm;                   // [BQ][1024]
    float* Qs  = sm + BQ * SEQ;        // [BQ][64]
    float* KVs = Qs + BQ * HD;         // [64][65]

    const int b  = blockIdx.z;
    const int h  = blockIdx.y;
    const int qb = blockIdx.x;
    const int q0 = qb * BQ;

    const float* Qp = g_q + ((size_t)(b * NH + h) * SEQ) * HD;
    const float* Kp = g_k + ((size_t)(b * NH + h) * SEQ) * HD;
    const float* Vp = g_v + ((size_t)(b * NH + h) * SEQ) * HD;

    const int tid = threadIdx.x;
    const int ty = tid >> 5;   // warp 0..7
    const int tx = tid & 31;   // lane

    {
        int r = tid >> 4;
        int c = (tid & 15) * 4;
        *(float4*)&Qs[r * HD + c] = *(const float4*)&Qp[(size_t)(q0 + r) * HD + c];
    }

    const float scale = 0.125f;  // 1/sqrt(64)

    // ---- scores ----
    for (int kt = 0; kt < SEQ / KT; kt++) {
        {
            int gg = tid >> 4;
            int c = (tid & 15) * 4;
            #pragma unroll
            for (int i = 0; i < 4; i++) {
                int r = gg * 4 + i;
                float4 kv = *(const float4*)&Kp[(size_t)(kt * KT + r) * HD + c];
                KVs[r * KVPAD + c + 0] = kv.x;
                KVs[r * KVPAD + c + 1] = kv.y;
                KVs[r * KVPAD + c + 2] = kv.z;
                KVs[r * KVPAD + c + 3] = kv.w;
            }
        }
        __syncthreads();

        float s00 = 0.f, s01 = 0.f, s10 = 0.f, s11 = 0.f;
        const float* q0p = &Qs[(ty * 2 + 0) * HD];
        const float* q1p = &Qs[(ty * 2 + 1) * HD];
        const float* k0p = &KVs[tx * KVPAD];
        const float* k1p = &KVs[(tx + 32) * KVPAD];
        #pragma unroll
        for (int d = 0; d < HD; d++) {
            float qa = q0p[d], qb2 = q1p[d];
            float ka = k0p[d], kb = k1p[d];
            s00 += qa * ka; s01 += qa * kb;
            s10 += qb2 * ka; s11 += qb2 * kb;
        }
        int kg0 = kt * KT + tx;
        int kg1 = kt * KT + tx + 32;
        int m0 = mask[b * SEQ + kg0];
        int m1 = mask[b * SEQ + kg1];
        S[(ty*2+0) * SEQ + kg0] = (m0 == 0) ? -1e30f : s00 * scale;
        S[(ty*2+0) * SEQ + kg1] = (m1 == 0) ? -1e30f : s01 * scale;
        S[(ty*2+1) * SEQ + kg0] = (m0 == 0) ? -1e30f : s10 * scale;
        S[(ty*2+1) * SEQ + kg1] = (m1 == 0) ? -1e30f : s11 * scale;
        __syncthreads();
    }

    // ---- softmax ----
    float inv[2];
    #pragma unroll
    for (int iq = 0; iq < 2; iq++) {
        float* row = &S[(ty * 2 + iq) * SEQ];
        float mx = -1e30f;
        for (int j = tx; j < SEQ; j += 32) mx = fmaxf(mx, row[j]);
        #pragma unroll
        for (int o = 16; o > 0; o >>= 1) mx = fmaxf(mx, __shfl_xor_sync(0xffffffff, mx, o));
        float sum = 0.f;
        for (int j = tx; j < SEQ; j += 32) {
            float e = __expf(row[j] - mx);
            row[j] = e;
            sum += e;
        }
        #pragma unroll
        for (int o = 16; o > 0; o >>= 1) sum += __shfl_xor_sync(0xffffffff, sum, o);
        inv[iq] = 1.f / sum;
    }

    // ---- P @ V ----
    float o00 = 0.f, o01 = 0.f, o10 = 0.f, o11 = 0.f;
    for (int kt = 0; kt < SEQ / KT; kt++) {
        __syncthreads();
        {
            int gg = tid >> 4;
            int c = (tid & 15) * 4;
            #pragma unroll
            for (int i = 0; i < 4; i++) {
                int r = gg * 4 + i;
                float4 vv = *(const float4*)&Vp[(size_t)(kt * KT + r) * HD + c];
                KVs[r * KVPAD + c + 0] = vv.x;
                KVs[r * KVPAD + c + 1] = vv.y;
                KVs[r * KVPAD + c + 2] = vv.z;
                KVs[r * KVPAD + c + 3] = vv.w;
            }
        }
        __syncthreads();

        const float* p0 = &S[(ty*2+0) * SEQ + kt * KT];
        const float* p1 = &S[(ty*2+1) * SEQ + kt * KT];
        #pragma unroll
        for (int kk = 0; kk < KT; kk++) {
            float pa = p0[kk], pb = p1[kk];
            float va = KVs[kk * KVPAD + tx];
            float vb = KVs[kk * KVPAD + tx + 32];
            o00 += pa * va; o01 += pa * vb;
            o10 += pb * va; o11 += pb * vb;
        }
    }

    {
        size_t base0 = ((size_t)(b * SEQ + q0 + ty*2 + 0)) * CDIM + h * HD;
        size_t base1 = ((size_t)(b * SEQ + q0 + ty*2 + 1)) * CDIM + h * HD;
        g_att[base0 + tx]      = o00 * inv[0];
        g_att[base0 + tx + 32] = o01 * inv[0];
        g_att[base1 + tx]      = o10 * inv[1];
        g_att[base1 + tx + 32] = o11 * inv[1];
    }
}

// ---------------------------------------------------------------------------
extern "C" void kernel_launch(void* const* d_in, const int* in_sizes, int n_in,
                              void* d_out, int out_size)
{
    const float* x      = (const float*)d_in[0];
    const int*   amask  = (const int*)  d_in[1];
    const float* W_attn = (const float*)d_in[2];
    const float* b_attn = (const float*)d_in[3];
    const float* W_proj = (const float*)d_in[4];
    const float* b_proj = (const float*)d_in[5];
    float* out = (float*)d_out;

    // 1) QKV GEMM (tf32 tensor cores) with scatter into g_q/g_k/g_v
    {
        dim3 grid(N3 / 128, (BATCH * SEQ) / 128);
        gemm_tc<1, CDIM, N3><<<grid, 256>>>(x, W_attn, b_attn, nullptr);
    }

    // 2) attention (fp32)
    {
        int smem = (BQ * SEQ + BQ * HD + KT * KVPAD) * (int)sizeof(float);
        cudaFuncSetAttribute(attn_kernel, cudaFuncAttributeMaxDynamicSharedMemorySize, smem);
        dim3 grid(SEQ / BQ, NH, BATCH);
        attn_kernel<<<grid, 256, smem>>>(amask);
    }

    // 3) proj GEMM (tf32 tensor cores; A = g_att read inside the kernel)
    {
        dim3 grid(CDIM / 128, (BATCH * SEQ) / 128);
        gemm_tc<0, CDIM, CDIM><<<grid, 256>>>(nullptr, W_proj, b_proj, out);
    }
}

// round 4
// speedup vs baseline: 4.6689x; 3.1116x over previous
#include <cuda_runtime.h>
#include <cuda_bf16.h>
#include <math.h>
#include <stdint.h>

#define BATCH 8
#define SEQ   1024
#define CDIM  768
#define NH    12
#define HD    64
#define N3    (3*CDIM)

// Scratch (no allocations allowed)
__device__ float g_q[BATCH*NH*SEQ*HD];
__device__ float g_k[BATCH*NH*SEQ*HD];
__device__ float g_v[BATCH*NH*SEQ*HD];
__device__ float g_att[BATCH*SEQ*CDIM];

// ---------------------------------------------------------------------------
// tf32 helpers
// ---------------------------------------------------------------------------
__device__ __forceinline__ uint32_t f2tf32(float x) {
    uint32_t u;
    asm("cvt.rna.tf32.f32 %0, %1;" : "=r"(u) : "f"(x));
    return u;
}

__device__ __forceinline__ void mma_tf32(float* c, const uint32_t* a, const uint32_t* b) {
    asm volatile(
        "mma.sync.aligned.m16n8k8.row.col.f32.tf32.tf32.f32 "
        "{%0,%1,%2,%3}, {%4,%5,%6,%7}, {%8,%9}, {%0,%1,%2,%3};"
        : "+f"(c[0]), "+f"(c[1]), "+f"(c[2]), "+f"(c[3])
        : "r"(a[0]), "r"(a[1]), "r"(a[2]), "r"(a[3]), "r"(b[0]), "r"(b[1]));
}

// ---------------------------------------------------------------------------
// Tensor-core GEMM (unchanged from round 3): C = A @ W + bias
// ---------------------------------------------------------------------------
#define LDA 36
#define LDB 136

template<int MODE, int K, int N>
__global__ __launch_bounds__(256)
void gemm_tc(const float* __restrict__ Ain,
             const float* __restrict__ W,
             const float* __restrict__ bias,
             float* __restrict__ Cout)
{
    const float* A = (MODE == 0) ? (const float*)g_att : Ain;

    __shared__ uint32_t As[128 * LDA];  // [m][k]
    __shared__ uint32_t Bs[32 * LDB];   // [k][n]

    const int tid  = threadIdx.x;
    const int bm   = blockIdx.y * 128;
    const int bn   = blockIdx.x * 128;
    const int warp = tid >> 5;
    const int lane = tid & 31;
    const int wm   = warp & 1;
    const int wn   = warp >> 1;
    const int g    = lane >> 2;
    const int t4   = lane & 3;

    float acc[4][4][4];
    #pragma unroll
    for (int mt = 0; mt < 4; mt++)
        #pragma unroll
        for (int nt = 0; nt < 4; nt++)
            #pragma unroll
            for (int i = 0; i < 4; i++) acc[mt][nt][i] = 0.f;

    for (int k0 = 0; k0 < K; k0 += 32) {
        #pragma unroll
        for (int i = 0; i < 4; i++) {
            int linear = tid + i * 256;
            int row = linear >> 3;
            int c4  = (linear & 7) * 4;
            float4 v = *(const float4*)&A[(size_t)(bm + row) * K + k0 + c4];
            uint4 u;
            u.x = f2tf32(v.x); u.y = f2tf32(v.y); u.z = f2tf32(v.z); u.w = f2tf32(v.w);
            *(uint4*)&As[row * LDA + c4] = u;
        }
        #pragma unroll
        for (int i = 0; i < 4; i++) {
            int linear = tid + i * 256;
            int row = linear >> 5;
            int c4  = (linear & 31) * 4;
            float4 v = *(const float4*)&W[(size_t)(k0 + row) * N + bn + c4];
            uint4 u;
            u.x = f2tf32(v.x); u.y = f2tf32(v.y); u.z = f2tf32(v.z); u.w = f2tf32(v.w);
            *(uint4*)&Bs[row * LDB + c4] = u;
        }
        __syncthreads();

        #pragma unroll
        for (int ks = 0; ks < 4; ks++) {
            const int kk = ks * 8;
            uint32_t a[4][4], b[4][2];
            #pragma unroll
            for (int mt = 0; mt < 4; mt++) {
                int m0 = wm * 64 + mt * 16 + g;
                a[mt][0] = As[(m0)     * LDA + kk + t4];
                a[mt][1] = As[(m0 + 8) * LDA + kk + t4];
                a[mt][2] = As[(m0)     * LDA + kk + t4 + 4];
                a[mt][3] = As[(m0 + 8) * LDA + kk + t4 + 4];
            }
            #pragma unroll
            for (int nt = 0; nt < 4; nt++) {
                int n0 = wn * 32 + nt * 8 + g;
                b[nt][0] = Bs[(kk + t4)     * LDB + n0];
                b[nt][1] = Bs[(kk + t4 + 4) * LDB + n0];
            }
            #pragma unroll
            for (int mt = 0; mt < 4; mt++)
                #pragma unroll
                for (int nt = 0; nt < 4; nt++)
                    mma_tf32(acc[mt][nt], a[mt], b[nt]);
        }
        __syncthreads();
    }

    #pragma unroll
    for (int mt = 0; mt < 4; mt++) {
        #pragma unroll
        for (int nt = 0; nt < 4; nt++) {
            #pragma unroll
            for (int i = 0; i < 4; i++) {
                int m = bm + wm * 64 + mt * 16 + g + (i >> 1) * 8;
                int n = bn + wn * 32 + nt * 8 + 2 * t4 + (i & 1);
                float v = acc[mt][nt][i] + bias[n];
                if (MODE == 0) {
                    Cout[(size_t)m * N + n] = v;
                } else {
                    int which = n / CDIM;
                    int c = n - which * CDIM;
                    int h = c >> 6;
                    int d = c & 63;
                    int b2 = m >> 10;
                    int t = m & 1023;
                    size_t idx = (((size_t)(b2 * NH + h) * SEQ) + t) * HD + d;
                    if (which == 0) g_q[idx] = v;
                    else if (which == 1) g_k[idx] = v;
                    else g_v[idx] = v;
                }
            }
        }
    }
}

// ---------------------------------------------------------------------------
// Flash attention, tf32 mma. One block = (b, h, 128 q-rows). 8 warps x 16 rows.
// Streams 64-key K/V tiles; online softmax in registers; P requantized to tf32
// through a per-warp smem pane for the P@V mma.
// smem pads chosen per access pattern (conflict-free): LDK=68, LDV=72, LDP=76.
// ---------------------------------------------------------------------------
#define BQT 128
#define LDK 68
#define LDV 72
#define LDP 76

__global__ __launch_bounds__(256)
void flash_attn(const int* __restrict__ mask)
{
    extern __shared__ uint32_t smu[];
    uint32_t* Ks = smu;                       // [64][LDK]
    uint32_t* Vs = Ks + 64 * LDK;             // [64][LDV]
    uint32_t* Ps = Vs + 64 * LDV;             // [128][LDP] (also Q staging)
    float* maskadd = (float*)(Ps + BQT * LDP); // [64]

    const int b  = blockIdx.z;
    const int h  = blockIdx.y;
    const int q0 = blockIdx.x * BQT;

    const float* Qp = g_q + ((size_t)(b * NH + h) * SEQ) * HD;
    const float* Kp = g_k + ((size_t)(b * NH + h) * SEQ) * HD;
    const float* Vp = g_v + ((size_t)(b * NH + h) * SEQ) * HD;

    const int tid  = threadIdx.x;
    const int warp = tid >> 5;
    const int lane = tid & 31;
    const int g    = lane >> 2;
    const int t4   = lane & 3;

    // ---- stage Q (scaled by 1/8, exact) into Ps, then preload fragments ----
    for (int i = tid; i < BQT * (HD / 4); i += 256) {
        int r = i >> 4;
        int c = (i & 15) * 4;
        float4 v = *(const float4*)&Qp[(size_t)(q0 + r) * HD + c];
        uint4 u;
        u.x = f2tf32(v.x * 0.125f); u.y = f2tf32(v.y * 0.125f);
        u.z = f2tf32(v.z * 0.125f); u.w = f2tf32(v.w * 0.125f);
        *(uint4*)&Ps[r * LDP + c] = u;
    }
    __syncthreads();

    uint32_t qf[8][4];
    {
        int r0 = warp * 16 + g;
        #pragma unroll
        for (int ks = 0; ks < 8; ks++) {
            int kk = ks * 8;
            qf[ks][0] = Ps[(r0)     * LDP + kk + t4];
            qf[ks][1] = Ps[(r0 + 8) * LDP + kk + t4];
            qf[ks][2] = Ps[(r0)     * LDP + kk + t4 + 4];
            qf[ks][3] = Ps[(r0 + 8) * LDP + kk + t4 + 4];
        }
    }
    __syncthreads();   // Ps will be reused for P

    float m0v = -1e30f, m1v = -1e30f;
    float l0 = 0.f, l1 = 0.f;
    float oacc[8][4];
    #pragma unroll
    for (int nt = 0; nt < 8; nt++)
        #pragma unroll
        for (int i = 0; i < 4; i++) oacc[nt][i] = 0.f;

    for (int kt = 0; kt < SEQ / 64; kt++) {
        // ---- load K,V 64x64 tiles (tf32) ----
        for (int i = tid; i < 64 * 16; i += 256) {
            int r = i >> 4;
            int c = (i & 15) * 4;
            float4 kv = *(const float4*)&Kp[(size_t)(kt * 64 + r) * HD + c];
            uint4 uk;
            uk.x = f2tf32(kv.x); uk.y = f2tf32(kv.y); uk.z = f2tf32(kv.z); uk.w = f2tf32(kv.w);
            *(uint4*)&Ks[r * LDK + c] = uk;
            float4 vv = *(const float4*)&Vp[(size_t)(kt * 64 + r) * HD + c];
            uint4 uv;
            uv.x = f2tf32(vv.x); uv.y = f2tf32(vv.y); uv.z = f2tf32(vv.z); uv.w = f2tf32(vv.w);
            *(uint4*)&Vs[r * LDV + c] = uv;
        }
        if (tid < 64)
            maskadd[tid] = (mask[b * SEQ + kt * 64 + tid] == 0) ? -1e30f : 0.f;
        __syncthreads();

        // ---- S = Q @ K^T  (rows g,g+8; cols nt*8 + 2t4 + {0,1}) ----
        float sacc[8][4];
        #pragma unroll
        for (int nt = 0; nt < 8; nt++)
            #pragma unroll
            for (int i = 0; i < 4; i++) sacc[nt][i] = 0.f;

        #pragma unroll
        for (int ks = 0; ks < 8; ks++) {
            int kk = ks * 8;
            #pragma unroll
            for (int nt = 0; nt < 8; nt++) {
                uint32_t bf[2];
                bf[0] = Ks[(nt * 8 + g) * LDK + kk + t4];
                bf[1] = Ks[(nt * 8 + g) * LDK + kk + t4 + 4];
                mma_tf32(sacc[nt], qf[ks], bf);
            }
        }

        // ---- mask + online softmax ----
        float tm0 = -1e30f, tm1 = -1e30f;
        #pragma unroll
        for (int nt = 0; nt < 8; nt++) {
            float ma = maskadd[nt * 8 + 2 * t4];
            float mb = maskadd[nt * 8 + 2 * t4 + 1];
            sacc[nt][0] += ma; sacc[nt][1] += mb;
            sacc[nt][2] += ma; sacc[nt][3] += mb;
            tm0 = fmaxf(tm0, fmaxf(sacc[nt][0], sacc[nt][1]));
            tm1 = fmaxf(tm1, fmaxf(sacc[nt][2], sacc[nt][3]));
        }
        tm0 = fmaxf(tm0, __shfl_xor_sync(0xffffffff, tm0, 1));
        tm0 = fmaxf(tm0, __shfl_xor_sync(0xffffffff, tm0, 2));
        tm1 = fmaxf(tm1, __shfl_xor_sync(0xffffffff, tm1, 1));
        tm1 = fmaxf(tm1, __shfl_xor_sync(0xffffffff, tm1, 2));

        float mn0 = fmaxf(m0v, tm0);
        float mn1 = fmaxf(m1v, tm1);
        float f0 = __expf(m0v - mn0);
        float f1 = __expf(m1v - mn1);
        m0v = mn0; m1v = mn1;
        l0 *= f0; l1 *= f1;
        #pragma unroll
        for (int nt = 0; nt < 8; nt++) {
            oacc[nt][0] *= f0; oacc[nt][1] *= f0;
            oacc[nt][2] *= f1; oacc[nt][3] *= f1;
        }

        int r0 = warp * 16 + g;
        float s0 = 0.f, s1 = 0.f;
        #pragma unroll
        for (int nt = 0; nt < 8; nt++) {
            float e0 = __expf(sacc[nt][0] - mn0);
            float e1 = __expf(sacc[nt][1] - mn0);
            float e2 = __expf(sacc[nt][2] - mn1);
            float e3 = __expf(sacc[nt][3] - mn1);
            s0 += e0 + e1;
            s1 += e2 + e3;
            Ps[(r0)     * LDP + nt * 8 + 2 * t4]     = f2tf32(e0);
            Ps[(r0)     * LDP + nt * 8 + 2 * t4 + 1] = f2tf32(e1);
            Ps[(r0 + 8) * LDP + nt * 8 + 2 * t4]     = f2tf32(e2);
            Ps[(r0 + 8) * LDP + nt * 8 + 2 * t4 + 1] = f2tf32(e3);
        }
        s0 += __shfl_xor_sync(0xffffffff, s0, 1);
        s0 += __shfl_xor_sync(0xffffffff, s0, 2);
        s1 += __shfl_xor_sync(0xffffffff, s1, 1);
        s1 += __shfl_xor_sync(0xffffffff, s1, 2);
        l0 += s0; l1 += s1;

        __syncwarp();   // Ps pane is warp-private

        // ---- O += P @ V ----
        #pragma unroll
        for (int ks = 0; ks < 8; ks++) {
            int kk = ks * 8;
            uint32_t af[4];
            af[0] = Ps[(r0)     * LDP + kk + t4];
            af[1] = Ps[(r0 + 8) * LDP + kk + t4];
            af[2] = Ps[(r0)     * LDP + kk + t4 + 4];
            af[3] = Ps[(r0 + 8) * LDP + kk + t4 + 4];
            #pragma unroll
            for (int nt = 0; nt < 8; nt++) {
                uint32_t bf[2];
                bf[0] = Vs[(kk + t4)     * LDV + nt * 8 + g];
                bf[1] = Vs[(kk + t4 + 4) * LDV + nt * 8 + g];
                mma_tf32(oacc[nt], af, bf);
            }
        }
        __syncthreads();   // before next K/V overwrite
    }

    // ---- epilogue: normalize and write g_att [B,T,C], C col = h*64 + d ----
    {
        float inv0 = 1.f / l0;
        float inv1 = 1.f / l1;
        int r0 = q0 + warp * 16 + g;
        size_t base0 = ((size_t)(b * SEQ + r0))     * CDIM + h * HD;
        size_t base1 = ((size_t)(b * SEQ + r0 + 8)) * CDIM + h * HD;
        #pragma unroll
        for (int nt = 0; nt < 8; nt++) {
            float2 v0 = make_float2(oacc[nt][0] * inv0, oacc[nt][1] * inv0);
            float2 v1 = make_float2(oacc[nt][2] * inv1, oacc[nt][3] * inv1);
            *(float2*)&g_att[base0 + nt * 8 + 2 * t4] = v0;
            *(float2*)&g_att[base1 + nt * 8 + 2 * t4] = v1;
        }
    }
}

// ---------------------------------------------------------------------------
extern "C" void kernel_launch(void* const* d_in, const int* in_sizes, int n_in,
                              void* d_out, int out_size)
{
    const float* x      = (const float*)d_in[0];
    const int*   amask  = (const int*)  d_in[1];
    const float* W_attn = (const float*)d_in[2];
    const float* b_attn = (const float*)d_in[3];
    const float* W_proj = (const float*)d_in[4];
    const float* b_proj = (const float*)d_in[5];
    float* out = (float*)d_out;

    // 1) QKV GEMM (tf32 tensor cores) -> g_q/g_k/g_v
    {
        dim3 grid(N3 / 128, (BATCH * SEQ) / 128);
        gemm_tc<1, CDIM, N3><<<grid, 256>>>(x, W_attn, b_attn, nullptr);
    }

    // 2) flash attention (tf32 tensor cores)
    {
        int smem = (64 * LDK + 64 * LDV + BQT * LDP + 64) * (int)sizeof(uint32_t);
        cudaFuncSetAttribute(flash_attn, cudaFuncAttributeMaxDynamicSharedMemorySize, smem);
        dim3 grid(SEQ / BQT, NH, BATCH);
        flash_attn<<<grid, 256, smem>>>(amask);
    }

    // 3) proj GEMM (tf32; A = g_att read device-side)
    {
        dim3 grid(CDIM / 128, (BATCH * SEQ) / 128);
        gemm_tc<0, CDIM, CDIM><<<grid, 256>>>(nullptr, W_proj, b_proj, out);
    }
}

// round 5
// speedup vs baseline: 5.3449x; 1.1448x over previous
#include <cuda_runtime.h>
#include <cuda_bf16.h>
#include <math.h>
#include <stdint.h>

#define BATCH 8
#define SEQ   1024
#define CDIM  768
#define NH    12
#define HD    64
#define N3    (3*CDIM)

// Scratch (tf32 bit patterns stored as uint32)
__device__ uint32_t g_q  [BATCH*NH*SEQ*HD];
__device__ uint32_t g_k  [BATCH*NH*SEQ*HD];
__device__ uint32_t g_v  [BATCH*NH*SEQ*HD];
__device__ uint32_t g_att[BATCH*SEQ*CDIM];
__device__ uint32_t g_xc [BATCH*SEQ*CDIM];
__device__ uint32_t g_wac[CDIM*N3];
__device__ uint32_t g_wpc[CDIM*CDIM];

// ---------------------------------------------------------------------------
// helpers
// ---------------------------------------------------------------------------
__device__ __forceinline__ uint32_t f2tf32(float x) {
    uint32_t u;
    asm("cvt.rna.tf32.f32 %0, %1;" : "=r"(u) : "f"(x));
    return u;
}

__device__ __forceinline__ void mma_tf32(float* c, const uint32_t* a, const uint32_t* b) {
    asm volatile(
        "mma.sync.aligned.m16n8k8.row.col.f32.tf32.tf32.f32 "
        "{%0,%1,%2,%3}, {%4,%5,%6,%7}, {%8,%9}, {%0,%1,%2,%3};"
        : "+f"(c[0]), "+f"(c[1]), "+f"(c[2]), "+f"(c[3])
        : "r"(a[0]), "r"(a[1]), "r"(a[2]), "r"(a[3]), "r"(b[0]), "r"(b[1]));
}

__device__ __forceinline__ void cpa16(uint32_t saddr, const void* gaddr) {
    asm volatile("cp.async.cg.shared.global [%0], [%1], 16;" :: "r"(saddr), "l"(gaddr));
}
__device__ __forceinline__ void cpa_commit() { asm volatile("cp.async.commit_group;"); }
template<int NN> __device__ __forceinline__ void cpa_wait() {
    asm volatile("cp.async.wait_group %0;" :: "n"(NN));
}

// ---------------------------------------------------------------------------
// Preconvert x, W_attn, W_proj to tf32 bit patterns (float4-wide).
// ---------------------------------------------------------------------------
#define XN4  (BATCH*SEQ*CDIM/4)
#define WAN4 (CDIM*N3/4)
#define WPN4 (CDIM*CDIM/4)

__global__ void preconvert(const float* __restrict__ x,
                           const float* __restrict__ wa,
                           const float* __restrict__ wp)
{
    int i = blockIdx.x * 256 + threadIdx.x;
    if (i < XN4) {
        float4 v = ((const float4*)x)[i];
        uint4 u = { f2tf32(v.x), f2tf32(v.y), f2tf32(v.z), f2tf32(v.w) };
        ((uint4*)g_xc)[i] = u;
    }
    if (i < WAN4) {
        float4 v = ((const float4*)wa)[i];
        uint4 u = { f2tf32(v.x), f2tf32(v.y), f2tf32(v.z), f2tf32(v.w) };
        ((uint4*)g_wac)[i] = u;
    }
    if (i < WPN4) {
        float4 v = ((const float4*)wp)[i];
        uint4 u = { f2tf32(v.x), f2tf32(v.y), f2tf32(v.z), f2tf32(v.w) };
        ((uint4*)g_wpc)[i] = u;
    }
}

// ---------------------------------------------------------------------------
// Tensor-core GEMM (tf32, fp32 accum), cp.async double-buffered.
// BM=128, BN=128, BK=32, 256 threads, 8 warps (2x4), 64x32 per warp.
// MODE 0: A = g_att, store fp32 + bias to Cout (proj).
// MODE 1: A = g_xc,  epilogue stores tf32 Q(*0.125)/K/V into g_q/g_k/g_v.
// ---------------------------------------------------------------------------
#define LDA 36
#define LDB 136

template<int MODE, int K, int N>
__global__ __launch_bounds__(256)
void gemm_tc(const float* __restrict__ bias, float* __restrict__ Cout)
{
    const uint32_t* A = (MODE == 0) ? (const uint32_t*)g_att : (const uint32_t*)g_xc;
    const uint32_t* W = (MODE == 0) ? (const uint32_t*)g_wpc : (const uint32_t*)g_wac;

    extern __shared__ uint32_t smg[];
    uint32_t* As = smg;                    // [2][128*LDA]
    uint32_t* Bs = smg + 2 * 128 * LDA;    // [2][32*LDB]
    const uint32_t sAs = (uint32_t)__cvta_generic_to_shared(As);
    const uint32_t sBs = (uint32_t)__cvta_generic_to_shared(Bs);

    const int tid  = threadIdx.x;
    const int bm   = blockIdx.y * 128;
    const int bn   = blockIdx.x * 128;
    const int warp = tid >> 5;
    const int lane = tid & 31;
    const int wm   = warp & 1;
    const int wn   = warp >> 1;
    const int g    = lane >> 2;
    const int t4   = lane & 3;

    float acc[4][4][4];
    #pragma unroll
    for (int mt = 0; mt < 4; mt++)
        #pragma unroll
        for (int nt = 0; nt < 4; nt++)
            #pragma unroll
            for (int i = 0; i < 4; i++) acc[mt][nt][i] = 0.f;

    const int NT = K / 32;

    // staging (4 float4 each for A and B per thread)
    auto stage = [&](int buf, int k0) {
        #pragma unroll
        for (int i = 0; i < 4; i++) {
            int linear = tid + i * 256;
            int row = linear >> 3;
            int c4  = (linear & 7) * 4;
            cpa16(sAs + (uint32_t)(buf * 128 * LDA + row * LDA + c4) * 4,
                  &A[(size_t)(bm + row) * K + k0 + c4]);
        }
        #pragma unroll
        for (int i = 0; i < 4; i++) {
            int linear = tid + i * 256;
            int row = linear >> 5;
            int c4  = (linear & 31) * 4;
            cpa16(sBs + (uint32_t)(buf * 32 * LDB + row * LDB + c4) * 4,
                  &W[(size_t)(k0 + row) * N + bn + c4]);
        }
        cpa_commit();
    };

    stage(0, 0);

    for (int kt = 0; kt < NT; kt++) {
        int buf = kt & 1;
        if (kt + 1 < NT) { stage(buf ^ 1, (kt + 1) * 32); cpa_wait<1>(); }
        else             { cpa_wait<0>(); }
        __syncthreads();

        const uint32_t* Ab = &As[buf * 128 * LDA];
        const uint32_t* Bb = &Bs[buf * 32 * LDB];

        #pragma unroll
        for (int ks = 0; ks < 4; ks++) {
            const int kk = ks * 8;
            uint32_t a[4][4], b[4][2];
            #pragma unroll
            for (int mt = 0; mt < 4; mt++) {
                int m0 = wm * 64 + mt * 16 + g;
                a[mt][0] = Ab[(m0)     * LDA + kk + t4];
                a[mt][1] = Ab[(m0 + 8) * LDA + kk + t4];
                a[mt][2] = Ab[(m0)     * LDA + kk + t4 + 4];
                a[mt][3] = Ab[(m0 + 8) * LDA + kk + t4 + 4];
            }
            #pragma unroll
            for (int nt = 0; nt < 4; nt++) {
                int n0 = wn * 32 + nt * 8 + g;
                b[nt][0] = Bb[(kk + t4)     * LDB + n0];
                b[nt][1] = Bb[(kk + t4 + 4) * LDB + n0];
            }
            #pragma unroll
            for (int mt = 0; mt < 4; mt++)
                #pragma unroll
                for (int nt = 0; nt < 4; nt++)
                    mma_tf32(acc[mt][nt], a[mt], b[nt]);
        }
        __syncthreads();
    }

    #pragma unroll
    for (int mt = 0; mt < 4; mt++) {
        #pragma unroll
        for (int nt = 0; nt < 4; nt++) {
            #pragma unroll
            for (int i = 0; i < 4; i++) {
                int m = bm + wm * 64 + mt * 16 + g + (i >> 1) * 8;
                int n = bn + wn * 32 + nt * 8 + 2 * t4 + (i & 1);
                float v = acc[mt][nt][i] + bias[n];
                if (MODE == 0) {
                    Cout[(size_t)m * N + n] = v;
                } else {
                    int which = n / CDIM;
                    int c = n - which * CDIM;
                    int h = c >> 6;
                    int d = c & 63;
                    int b2 = m >> 10;
                    int t = m & 1023;
                    size_t idx = (((size_t)(b2 * NH + h) * SEQ) + t) * HD + d;
                    if (which == 0)      g_q[idx] = f2tf32(v * 0.125f);
                    else if (which == 1) g_k[idx] = f2tf32(v);
                    else                 g_v[idx] = f2tf32(v);
                }
            }
        }
    }
}

// ---------------------------------------------------------------------------
// Flash attention (tf32 mma), cp.async double-buffered K/V tiles.
// One block = (b, h, 128 q-rows). 8 warps x 16 rows. Inputs already tf32.
// ---------------------------------------------------------------------------
#define BQT 128
#define LDK 68
#define LDV 72
#define LDP 76

__global__ __launch_bounds__(256)
void flash_attn(const int* __restrict__ mask)
{
    extern __shared__ uint32_t smu[];
    uint32_t* Ks = smu;                        // [2][64*LDK]
    uint32_t* Vs = smu + 2 * 64 * LDK;         // [2][64*LDV]
    uint32_t* Ps = Vs + 2 * 64 * LDV;          // [128*LDP]
    float* maskf = (float*)(Ps + BQT * LDP);   // [2][64]
    const uint32_t sKs = (uint32_t)__cvta_generic_to_shared(Ks);
    const uint32_t sVs = (uint32_t)__cvta_generic_to_shared(Vs);
    const uint32_t sPs = (uint32_t)__cvta_generic_to_shared(Ps);

    const int b  = blockIdx.z;
    const int h  = blockIdx.y;
    const int q0 = blockIdx.x * BQT;

    const uint32_t* Qp = g_q + ((size_t)(b * NH + h) * SEQ) * HD;
    const uint32_t* Kp = g_k + ((size_t)(b * NH + h) * SEQ) * HD;
    const uint32_t* Vp = g_v + ((size_t)(b * NH + h) * SEQ) * HD;

    const int tid  = threadIdx.x;
    const int warp = tid >> 5;
    const int lane = tid & 31;
    const int g    = lane >> 2;
    const int t4   = lane & 3;

    auto stage_kv = [&](int buf, int kt) {
        for (int i = tid; i < 64 * 16; i += 256) {
            int r = i >> 4;
            int c = (i & 15) * 4;
            cpa16(sKs + (uint32_t)(buf * 64 * LDK + r * LDK + c) * 4,
                  &Kp[(size_t)(kt * 64 + r) * HD + c]);
            cpa16(sVs + (uint32_t)(buf * 64 * LDV + r * LDV + c) * 4,
                  &Vp[(size_t)(kt * 64 + r) * HD + c]);
        }
        cpa_commit();
        if (tid < 64)
            maskf[buf * 64 + tid] = (mask[b * SEQ + kt * 64 + tid] == 0) ? -1e30f : 0.f;
    };

    // ---- stage Q (already tf32 & pre-scaled) into Ps via cp.async ----
    for (int i = tid; i < BQT * 16; i += 256) {
        int r = i >> 4;
        int c = (i & 15) * 4;
        cpa16(sPs + (uint32_t)(r * LDP + c) * 4, &Qp[(size_t)(q0 + r) * HD + c]);
    }
    cpa_commit();
    stage_kv(0, 0);
    cpa_wait<1>();     // Q group done; kv(0) may still be in flight
    __syncthreads();

    uint32_t qf[8][4];
    {
        int r0 = warp * 16 + g;
        #pragma unroll
        for (int ks = 0; ks < 8; ks++) {
            int kk = ks * 8;
            qf[ks][0] = Ps[(r0)     * LDP + kk + t4];
            qf[ks][1] = Ps[(r0 + 8) * LDP + kk + t4];
            qf[ks][2] = Ps[(r0)     * LDP + kk + t4 + 4];
            qf[ks][3] = Ps[(r0 + 8) * LDP + kk + t4 + 4];
        }
    }
    __syncthreads();   // Ps reused as P pane

    float m0v = -1e30f, m1v = -1e30f;
    float l0 = 0.f, l1 = 0.f;
    float oacc[8][4];
    #pragma unroll
    for (int nt = 0; nt < 8; nt++)
        #pragma unroll
        for (int i = 0; i < 4; i++) oacc[nt][i] = 0.f;

    const int NT = SEQ / 64;
    for (int kt = 0; kt < NT; kt++) {
        int buf = kt & 1;
        if (kt + 1 < NT) { stage_kv(buf ^ 1, kt + 1); cpa_wait<1>(); }
        else             { cpa_wait<0>(); }
        __syncthreads();

        const uint32_t* Kb = &Ks[buf * 64 * LDK];
        const uint32_t* Vb = &Vs[buf * 64 * LDV];
        const float* mb = &maskf[buf * 64];

        // ---- S = Q @ K^T ----
        float sacc[8][4];
        #pragma unroll
        for (int nt = 0; nt < 8; nt++)
            #pragma unroll
            for (int i = 0; i < 4; i++) sacc[nt][i] = 0.f;

        #pragma unroll
        for (int ks = 0; ks < 8; ks++) {
            int kk = ks * 8;
            #pragma unroll
            for (int nt = 0; nt < 8; nt++) {
                uint32_t bf[2];
                bf[0] = Kb[(nt * 8 + g) * LDK + kk + t4];
                bf[1] = Kb[(nt * 8 + g) * LDK + kk + t4 + 4];
                mma_tf32(sacc[nt], qf[ks], bf);
            }
        }

        // ---- mask + online softmax ----
        float tm0 = -1e30f, tm1 = -1e30f;
        #pragma unroll
        for (int nt = 0; nt < 8; nt++) {
            float ma = mb[nt * 8 + 2 * t4];
            float mb2 = mb[nt * 8 + 2 * t4 + 1];
            sacc[nt][0] += ma; sacc[nt][1] += mb2;
            sacc[nt][2] += ma; sacc[nt][3] += mb2;
            tm0 = fmaxf(tm0, fmaxf(sacc[nt][0], sacc[nt][1]));
            tm1 = fmaxf(tm1, fmaxf(sacc[nt][2], sacc[nt][3]));
        }
        tm0 = fmaxf(tm0, __shfl_xor_sync(0xffffffff, tm0, 1));
        tm0 = fmaxf(tm0, __shfl_xor_sync(0xffffffff, tm0, 2));
        tm1 = fmaxf(tm1, __shfl_xor_sync(0xffffffff, tm1, 1));
        tm1 = fmaxf(tm1, __shfl_xor_sync(0xffffffff, tm1, 2));

        float mn0 = fmaxf(m0v, tm0);
        float mn1 = fmaxf(m1v, tm1);
        float f0 = __expf(m0v - mn0);
        float f1 = __expf(m1v - mn1);
        m0v = mn0; m1v = mn1;
        l0 *= f0; l1 *= f1;
        #pragma unroll
        for (int nt = 0; nt < 8; nt++) {
            oacc[nt][0] *= f0; oacc[nt][1] *= f0;
            oacc[nt][2] *= f1; oacc[nt][3] *= f1;
        }

        int r0 = warp * 16 + g;
        float s0 = 0.f, s1 = 0.f;
        #pragma unroll
        for (int nt = 0; nt < 8; nt++) {
            float e0 = __expf(sacc[nt][0] - mn0);
            float e1 = __expf(sacc[nt][1] - mn0);
            float e2 = __expf(sacc[nt][2] - mn1);
            float e3 = __expf(sacc[nt][3] - mn1);
            s0 += e0 + e1;
            s1 += e2 + e3;
            Ps[(r0)     * LDP + nt * 8 + 2 * t4]     = f2tf32(e0);
            Ps[(r0)     * LDP + nt * 8 + 2 * t4 + 1] = f2tf32(e1);
            Ps[(r0 + 8) * LDP + nt * 8 + 2 * t4]     = f2tf32(e2);
            Ps[(r0 + 8) * LDP + nt * 8 + 2 * t4 + 1] = f2tf32(e3);
        }
        s0 += __shfl_xor_sync(0xffffffff, s0, 1);
        s0 += __shfl_xor_sync(0xffffffff, s0, 2);
        s1 += __shfl_xor_sync(0xffffffff, s1, 1);
        s1 += __shfl_xor_sync(0xffffffff, s1, 2);
        l0 += s0; l1 += s1;

        __syncwarp();  // Ps pane is warp-private

        // ---- O += P @ V ----
        #pragma unroll
        for (int ks = 0; ks < 8; ks++) {
            int kk = ks * 8;
            uint32_t af[4];
            af[0] = Ps[(r0)     * LDP + kk + t4];
            af[1] = Ps[(r0 + 8) * LDP + kk + t4];
            af[2] = Ps[(r0)     * LDP + kk + t4 + 4];
            af[3] = Ps[(r0 + 8) * LDP + kk + t4 + 4];
            #pragma unroll
            for (int nt = 0; nt < 8; nt++) {
                uint32_t bf[2];
                bf[0] = Vb[(kk + t4)     * LDV + nt * 8 + g];
                bf[1] = Vb[(kk + t4 + 4) * LDV + nt * 8 + g];
                mma_tf32(oacc[nt], af, bf);
            }
        }
        __syncthreads();
    }

    // ---- epilogue: normalize, convert to tf32, write g_att ----
    {
        float inv0 = 1.f / l0;
        float inv1 = 1.f / l1;
        int r0 = q0 + warp * 16 + g;
        size_t base0 = ((size_t)(b * SEQ + r0))     * CDIM + h * HD;
        size_t base1 = ((size_t)(b * SEQ + r0 + 8)) * CDIM + h * HD;
        #pragma unroll
        for (int nt = 0; nt < 8; nt++) {
            uint2 v0 = make_uint2(f2tf32(oacc[nt][0] * inv0), f2tf32(oacc[nt][1] * inv0));
            uint2 v1 = make_uint2(f2tf32(oacc[nt][2] * inv1), f2tf32(oacc[nt][3] * inv1));
            *(uint2*)&g_att[base0 + nt * 8 + 2 * t4] = v0;
            *(uint2*)&g_att[base1 + nt * 8 + 2 * t4] = v1;
        }
    }
}

// ---------------------------------------------------------------------------
extern "C" void kernel_launch(void* const* d_in, const int* in_sizes, int n_in,
                              void* d_out, int out_size)
{
    const float* x      = (const float*)d_in[0];
    const int*   amask  = (const int*)  d_in[1];
    const float* W_attn = (const float*)d_in[2];
    const float* b_attn = (const float*)d_in[3];
    const float* W_proj = (const float*)d_in[4];
    const float* b_proj = (const float*)d_in[5];
    float* out = (float*)d_out;

    // 0) preconvert inputs to tf32
    preconvert<<<(XN4 + 255) / 256, 256>>>(x, W_attn, W_proj);

    const int gemm_smem = (2 * 128 * LDA + 2 * 32 * LDB) * (int)sizeof(uint32_t);

    // 1) QKV GEMM -> tf32 g_q/g_k/g_v
    {
        cudaFuncSetAttribute(gemm_tc<1, CDIM, N3>,
                             cudaFuncAttributeMaxDynamicSharedMemorySize, gemm_smem);
        dim3 grid(N3 / 128, (BATCH * SEQ) / 128);
        gemm_tc<1, CDIM, N3><<<grid, 256, gemm_smem>>>(b_attn, nullptr);
    }

    // 2) flash attention -> tf32 g_att
    {
        int smem = (2 * 64 * LDK + 2 * 64 * LDV + BQT * LDP + 128) * (int)sizeof(uint32_t);
        cudaFuncSetAttribute(flash_attn, cudaFuncAttributeMaxDynamicSharedMemorySize, smem);
        dim3 grid(SEQ / BQT, NH, BATCH);
        flash_attn<<<grid, 256, smem>>>(amask);
    }

    // 3) proj GEMM -> out (fp32 + bias)
    {
        cudaFuncSetAttribute(gemm_tc<0, CDIM, CDIM>,
                             cudaFuncAttributeMaxDynamicSharedMemorySize, gemm_smem);
        dim3 grid(CDIM / 128, (BATCH * SEQ) / 128);
        gemm_tc<0, CDIM, CDIM><<<grid, 256, gemm_smem>>>(b_proj, out);
    }
}

// round 8
// speedup vs baseline: 8.4975x; 1.5898x over previous
#include <cuda_runtime.h>
#include <cuda_fp16.h>
#include <math.h>
#include <stdint.h>

#define BATCH 8
#define SEQ   1024
#define CDIM  768
#define NH    12
#define HD    64
#define N3    (3*CDIM)

// Scratch: fp16 payloads stored in uint32 arrays (guaranteed 4B alignment).
__device__ uint32_t g_q  [BATCH*NH*SEQ*HD/2];   // [B,H,T,D] half, pre-scaled 1/8
__device__ uint32_t g_k  [BATCH*NH*SEQ*HD/2];   // [B,H,T,D] half
__device__ uint32_t g_vT [BATCH*NH*SEQ*HD/2];   // [B,H,D,T] half (transposed!)
__device__ uint32_t g_att[BATCH*SEQ*CDIM/2];    // [B,T,C] half
__device__ uint32_t g_xc [BATCH*SEQ*CDIM/2];    // x in half
__device__ uint32_t g_wat[N3*CDIM/2];           // W_attn^T [N3][CDIM] half
__device__ uint32_t g_wpt[CDIM*CDIM/2];         // W_proj^T [CDIM][CDIM] half

// ---------------------------------------------------------------------------
// helpers
// ---------------------------------------------------------------------------
__device__ __forceinline__ uint32_t f2h2(float a, float b) {
    __half2 h = __floats2half2_rn(a, b);
    return *(uint32_t*)&h;
}

__device__ __forceinline__ void mma_f16(float* c, const uint32_t* a, const uint32_t* b) {
    asm volatile(
        "mma.sync.aligned.m16n8k16.row.col.f32.f16.f16.f32 "
        "{%0,%1,%2,%3}, {%4,%5,%6,%7}, {%8,%9}, {%0,%1,%2,%3};"
        : "+f"(c[0]), "+f"(c[1]), "+f"(c[2]), "+f"(c[3])
        : "r"(a[0]), "r"(a[1]), "r"(a[2]), "r"(a[3]), "r"(b[0]), "r"(b[1]));
}

__device__ __forceinline__ void cpa16(uint32_t saddr, const void* gaddr) {
    asm volatile("cp.async.cg.shared.global [%0], [%1], 16;" :: "r"(saddr), "l"(gaddr));
}
__device__ __forceinline__ void cpa_commit() { asm volatile("cp.async.commit_group;"); }
template<int NN> __device__ __forceinline__ void cpa_wait() {
    asm volatile("cp.async.wait_group %0;" :: "n"(NN));
}
__device__ __forceinline__ uint32_t smem_u32(const void* p) {
    return (uint32_t)__cvta_generic_to_shared(p);
}

// ---------------------------------------------------------------------------
// Preconvert / transpose kernels
// ---------------------------------------------------------------------------
#define XN4 (BATCH*SEQ*CDIM/4)

__global__ void preconvert_x(const float* __restrict__ x)
{
    int i = blockIdx.x * 256 + threadIdx.x;
    if (i < XN4) {
        float4 v = ((const float4*)x)[i];
        uint2 u = { f2h2(v.x, v.y), f2h2(v.z, v.w) };
        ((uint2*)g_xc)[i] = u;
    }
}

// transpose W[K][N] -> Wt[N][K] half. WSEL 0: g_wat, 1: g_wpt.
template<int WSEL, int K, int N>
__global__ void transpose_w(const float* __restrict__ w)
{
    __half* wt = (WSEL == 0) ? (__half*)g_wat : (__half*)g_wpt;
    __shared__ float t[32][33];
    int n0 = blockIdx.x * 32, k0 = blockIdx.y * 32;
    int tx = threadIdx.x, ty = threadIdx.y;   // 32 x 8
    #pragma unroll
    for (int i = 0; i < 32; i += 8)
        t[ty + i][tx] = w[(size_t)(k0 + ty + i) * N + n0 + tx];
    __syncthreads();
    #pragma unroll
    for (int i = 0; i < 32; i += 8)
        wt[(size_t)(n0 + ty + i) * K + k0 + tx] = __float2half(t[tx][ty + i]);
}

// ---------------------------------------------------------------------------
// fp16 tensor-core GEMM: C[M,N] = A[M,K] @ Wt[N,K]^T + bias   (f32 accum)
// BM=128, BN=128, BK=64 halves. 256 threads, 8 warps (2x4), 64x32 per warp.
// smem rows stored as half2 words, stride LD2=36 (conflict-free fragments).
// MODE 0: A=g_att, W=g_wpt, fp32 out + bias.
// MODE 1: A=g_xc,  W=g_wat, scatter half q(x0.125)/k/vT.
// ---------------------------------------------------------------------------
#define LD2 36
#define TW  (128 * LD2)   // words per tile buffer

template<int MODE, int K, int N>
__global__ __launch_bounds__(256)
void gemm_h(const float* __restrict__ bias, float* __restrict__ Cout)
{
    const uint32_t* A2 = (MODE == 0) ? g_att : g_xc;   // [M][K/2]
    const uint32_t* W2 = (MODE == 0) ? g_wpt : g_wat;  // [N][K/2]
    const int K2 = K / 2;

    extern __shared__ uint32_t sm[];
    uint32_t* As = sm;            // [2][128][LD2]
    uint32_t* Bs = sm + 2 * TW;   // [2][128][LD2]
    const uint32_t sAs = smem_u32(As);
    const uint32_t sBs = smem_u32(Bs);

    const int tid  = threadIdx.x;
    const int bm   = blockIdx.y * 128;
    const int bn   = blockIdx.x * 128;
    const int warp = tid >> 5;
    const int lane = tid & 31;
    const int wm   = warp & 1;
    const int wn   = warp >> 1;
    const int g    = lane >> 2;
    const int t4   = lane & 3;

    float acc[4][4][4];
    #pragma unroll
    for (int mt = 0; mt < 4; mt++)
        #pragma unroll
        for (int nt = 0; nt < 4; nt++)
            #pragma unroll
            for (int i = 0; i < 4; i++) acc[mt][nt][i] = 0.f;

    const int NC = K / 64;

    auto stage = [&](int buf, int k0w) {   // k0w = k offset in half2 words
        #pragma unroll
        for (int it = 0; it < 4; it++) {
            int i = tid + it * 256;        // 0..1023
            int r = i >> 3, c = i & 7;     // row 0..127, 16B chunk 0..7
            cpa16(sAs + (uint32_t)(buf * TW + r * LD2 + c * 4) * 4,
                  &A2[(size_t)(bm + r) * K2 + k0w + c * 4]);
        }
        #pragma unroll
        for (int it = 0; it < 4; it++) {
            int i = tid + it * 256;
            int r = i >> 3, c = i & 7;
            cpa16(sBs + (uint32_t)(buf * TW + r * LD2 + c * 4) * 4,
                  &W2[(size_t)(bn + r) * K2 + k0w + c * 4]);
        }
        cpa_commit();
    };

    stage(0, 0);
    for (int ck = 0; ck < NC; ck++) {
        int buf = ck & 1;
        if (ck + 1 < NC) { stage(buf ^ 1, (ck + 1) * 32); cpa_wait<1>(); }
        else             { cpa_wait<0>(); }
        __syncthreads();

        const uint32_t* Ab = &As[buf * TW];
        const uint32_t* Bb = &Bs[buf * TW];

        #pragma unroll
        for (int ks = 0; ks < 4; ks++) {       // 4 x k16
            const int kk2 = ks * 8;
            uint32_t a[4][4], b[4][2];
            #pragma unroll
            for (int mt = 0; mt < 4; mt++) {
                int m0 = wm * 64 + mt * 16 + g;
                a[mt][0] = Ab[(m0)     * LD2 + kk2 + t4];
                a[mt][1] = Ab[(m0 + 8) * LD2 + kk2 + t4];
                a[mt][2] = Ab[(m0)     * LD2 + kk2 + t4 + 4];
                a[mt][3] = Ab[(m0 + 8) * LD2 + kk2 + t4 + 4];
            }
            #pragma unroll
            for (int nt = 0; nt < 4; nt++) {
                int n0 = wn * 32 + nt * 8 + g;
                b[nt][0] = Bb[(n0) * LD2 + kk2 + t4];
                b[nt][1] = Bb[(n0) * LD2 + kk2 + t4 + 4];
            }
            #pragma unroll
            for (int mt = 0; mt < 4; mt++)
                #pragma unroll
                for (int nt = 0; nt < 4; nt++)
                    mma_f16(acc[mt][nt], a[mt], b[nt]);
        }
        __syncthreads();
    }

    // ---- epilogue ----
    #pragma unroll
    for (int mt = 0; mt < 4; mt++) {
        #pragma unroll
        for (int nt = 0; nt < 4; nt++) {
            #pragma unroll
            for (int i = 0; i < 4; i++) {
                int m = bm + wm * 64 + mt * 16 + g + (i >> 1) * 8;
                int n = bn + wn * 32 + nt * 8 + 2 * t4 + (i & 1);
                float v = acc[mt][nt][i] + bias[n];
                if (MODE == 0) {
                    Cout[(size_t)m * N + n] = v;
                } else {
                    int which = n / CDIM;
                    int c = n - which * CDIM;
                    int h = c >> 6;
                    int d = c & 63;
                    int b2 = m >> 10;
                    int t = m & 1023;
                    if (which == 0) {
                        size_t idx = (((size_t)(b2 * NH + h) * SEQ) + t) * HD + d;
                        ((__half*)g_q)[idx] = __float2half(v * 0.125f);
                    } else if (which == 1) {
                        size_t idx = (((size_t)(b2 * NH + h) * SEQ) + t) * HD + d;
                        ((__half*)g_k)[idx] = __float2half(v);
                    } else {
                        size_t idx = (((size_t)(b2 * NH + h) * HD) + d) * SEQ + t;
                        ((__half*)g_vT)[idx] = __float2half(v);
                    }
                }
            }
        }
    }
}

// ---------------------------------------------------------------------------
// Flash attention, fp16 mma. One block = (b, h, 128 q-rows), 8 warps x 16 rows.
// K tiles [key][d] half2; V tiles from g_vT [d][key] half2; P pane half2.
// ---------------------------------------------------------------------------
#define BQT 128
#define LDF 36            // half2 stride for 64-half rows (Ks/Vs/Ps)
#define KVW (64 * LDF)    // words per K or V buffer

__global__ __launch_bounds__(256)
void flash_attn(const int* __restrict__ mask)
{
    extern __shared__ uint32_t smu[];
    uint32_t* Ks = smu;                       // [2][64][LDF]
    uint32_t* Vs = smu + 2 * KVW;             // [2][64][LDF]
    uint32_t* Ps = Vs + 2 * KVW;              // [128][LDF]   (Q staging, then P)
    float* maskf = (float*)(Ps + BQT * LDF);  // [2][64]
    const uint32_t sKs = smem_u32(Ks);
    const uint32_t sVs = smem_u32(Vs);
    const uint32_t sPs = smem_u32(Ps);

    const int b  = blockIdx.z;
    const int h  = blockIdx.y;
    const int q0 = blockIdx.x * BQT;

    const uint32_t* Qp2 = g_q  + ((size_t)(b * NH + h) * SEQ) * (HD / 2);
    const uint32_t* Kp2 = g_k  + ((size_t)(b * NH + h) * SEQ) * (HD / 2);
    const uint32_t* Vt2 = g_vT + ((size_t)(b * NH + h) * HD) * (SEQ / 2);

    const int tid  = threadIdx.x;
    const int warp = tid >> 5;
    const int lane = tid & 31;
    const int g    = lane >> 2;
    const int t4   = lane & 3;

    auto stage_kv = [&](int buf, int kt) {
        // K tile: 64 rows (key) x 32 half2 (d); 2 chunks/thread
        #pragma unroll
        for (int it = 0; it < 2; it++) {
            int i = tid + it * 256;            // 0..511
            int r = i >> 3, c = i & 7;
            cpa16(sKs + (uint32_t)(buf * KVW + r * LDF + c * 4) * 4,
                  &Kp2[(size_t)(kt * 64 + r) * 32 + c * 4]);
        }
        // V^T tile: 64 rows (d) x 32 half2 (key)
        #pragma unroll
        for (int it = 0; it < 2; it++) {
            int i = tid + it * 256;
            int r = i >> 3, c = i & 7;
            cpa16(sVs + (uint32_t)(buf * KVW + r * LDF + c * 4) * 4,
                  &Vt2[(size_t)r * (SEQ / 2) + kt * 32 + c * 4]);
        }
        cpa_commit();
        if (tid < 64)
            maskf[buf * 64 + tid] = (mask[b * SEQ + kt * 64 + tid] == 0) ? -1e30f : 0.f;
    };

    // ---- stage Q (half, pre-scaled) into Ps ----
    #pragma unroll
    for (int it = 0; it < 4; it++) {
        int i = tid + it * 256;               // 0..1023
        int r = i >> 3, c = i & 7;
        cpa16(sPs + (uint32_t)(r * LDF + c * 4) * 4,
              &Qp2[(size_t)(q0 + r) * 32 + c * 4]);
    }
    cpa_commit();
    stage_kv(0, 0);
    cpa_wait<1>();
    __syncthreads();

    uint32_t qf[4][4];
    {
        int r0 = warp * 16 + g;
        #pragma unroll
        for (int ks = 0; ks < 4; ks++) {
            int kk2 = ks * 8;
            qf[ks][0] = Ps[(r0)     * LDF + kk2 + t4];
            qf[ks][1] = Ps[(r0 + 8) * LDF + kk2 + t4];
            qf[ks][2] = Ps[(r0)     * LDF + kk2 + t4 + 4];
            qf[ks][3] = Ps[(r0 + 8) * LDF + kk2 + t4 + 4];
        }
    }
    __syncthreads();   // Ps reused as P pane

    float m0v = -1e30f, m1v = -1e30f;
    float l0 = 0.f, l1 = 0.f;
    float oacc[8][4];
    #pragma unroll
    for (int nt = 0; nt < 8; nt++)
        #pragma unroll
        for (int i = 0; i < 4; i++) oacc[nt][i] = 0.f;

    const int NT = SEQ / 64;
    for (int kt = 0; kt < NT; kt++) {
        int buf = kt & 1;
        if (kt + 1 < NT) { stage_kv(buf ^ 1, kt + 1); cpa_wait<1>(); }
        else             { cpa_wait<0>(); }
        __syncthreads();

        const uint32_t* Kb = &Ks[buf * KVW];
        const uint32_t* Vb = &Vs[buf * KVW];
        const float* mb = &maskf[buf * 64];

        // ---- S = Q @ K^T ----
        float sacc[8][4];
        #pragma unroll
        for (int nt = 0; nt < 8; nt++)
            #pragma unroll
            for (int i = 0; i < 4; i++) sacc[nt][i] = 0.f;

        #pragma unroll
        for (int ks = 0; ks < 4; ks++) {
            int kk2 = ks * 8;
            #pragma unroll
            for (int nt = 0; nt < 8; nt++) {
                uint32_t bf[2];
                bf[0] = Kb[(nt * 8 + g) * LDF + kk2 + t4];
                bf[1] = Kb[(nt * 8 + g) * LDF + kk2 + t4 + 4];
                mma_f16(sacc[nt], qf[ks], bf);
            }
        }

        // ---- mask + online softmax ----
        float tm0 = -1e30f, tm1 = -1e30f;
        #pragma unroll
        for (int nt = 0; nt < 8; nt++) {
            float ma  = mb[nt * 8 + 2 * t4];
            float mb2 = mb[nt * 8 + 2 * t4 + 1];
            sacc[nt][0] += ma; sacc[nt][1] += mb2;
            sacc[nt][2] += ma; sacc[nt][3] += mb2;
            tm0 = fmaxf(tm0, fmaxf(sacc[nt][0], sacc[nt][1]));
            tm1 = fmaxf(tm1, fmaxf(sacc[nt][2], sacc[nt][3]));
        }
        tm0 = fmaxf(tm0, __shfl_xor_sync(0xffffffff, tm0, 1));
        tm0 = fmaxf(tm0, __shfl_xor_sync(0xffffffff, tm0, 2));
        tm1 = fmaxf(tm1, __shfl_xor_sync(0xffffffff, tm1, 1));
        tm1 = fmaxf(tm1, __shfl_xor_sync(0xffffffff, tm1, 2));

        float mn0 = fmaxf(m0v, tm0);
        float mn1 = fmaxf(m1v, tm1);
        float f0 = __expf(m0v - mn0);
        float f1 = __expf(m1v - mn1);
        m0v = mn0; m1v = mn1;
        l0 *= f0; l1 *= f1;
        #pragma unroll
        for (int nt = 0; nt < 8; nt++) {
            oacc[nt][0] *= f0; oacc[nt][1] *= f0;
            oacc[nt][2] *= f1; oacc[nt][3] *= f1;
        }

        int r0 = warp * 16 + g;
        float s0 = 0.f, s1 = 0.f;
        #pragma unroll
        for (int nt = 0; nt < 8; nt++) {
            float e0 = __expf(sacc[nt][0] - mn0);
            float e1 = __expf(sacc[nt][1] - mn0);
            float e2 = __expf(sacc[nt][2] - mn1);
            float e3 = __expf(sacc[nt][3] - mn1);
            s0 += e0 + e1;
            s1 += e2 + e3;
            Ps[(r0)     * LDF + nt * 4 + t4] = f2h2(e0, e1);
            Ps[(r0 + 8) * LDF + nt * 4 + t4] = f2h2(e2, e3);
        }
        s0 += __shfl_xor_sync(0xffffffff, s0, 1);
        s0 += __shfl_xor_sync(0xffffffff, s0, 2);
        s1 += __shfl_xor_sync(0xffffffff, s1, 1);
        s1 += __shfl_xor_sync(0xffffffff, s1, 2);
        l0 += s0; l1 += s1;

        __syncwarp();   // P pane is warp-private

        // ---- O += P @ V ----
        #pragma unroll
        for (int ks = 0; ks < 4; ks++) {
            int kk2 = ks * 8;
            uint32_t af[4];
            af[0] = Ps[(r0)     * LDF + kk2 + t4];
            af[1] = Ps[(r0 + 8) * LDF + kk2 + t4];
            af[2] = Ps[(r0)     * LDF + kk2 + t4 + 4];
            af[3] = Ps[(r0 + 8) * LDF + kk2 + t4 + 4];
            #pragma unroll
            for (int nt = 0; nt < 8; nt++) {
                uint32_t bf[2];
                bf[0] = Vb[(nt * 8 + g) * LDF + kk2 + t4];
                bf[1] = Vb[(nt * 8 + g) * LDF + kk2 + t4 + 4];
                mma_f16(oacc[nt], af, bf);
            }
        }
        __syncthreads();
    }

    // ---- epilogue: normalize, write g_att (half2) ----
    {
        float inv0 = 1.f / l0;
        float inv1 = 1.f / l1;
        int r0 = q0 + warp * 16 + g;
        size_t base0 = ((size_t)(b * SEQ + r0))     * (CDIM / 2) + h * (HD / 2);
        size_t base1 = ((size_t)(b * SEQ + r0 + 8)) * (CDIM / 2) + h * (HD / 2);
        #pragma unroll
        for (int nt = 0; nt < 8; nt++) {
            g_att[base0 + nt * 4 + t4] = f2h2(oacc[nt][0] * inv0, oacc[nt][1] * inv0);
            g_att[base1 + nt * 4 + t4] = f2h2(oacc[nt][2] * inv1, oacc[nt][3] * inv1);
        }
    }
}

// ---------------------------------------------------------------------------
extern "C" void kernel_launch(void* const* d_in, const int* in_sizes, int n_in,
                              void* d_out, int out_size)
{
    const float* x      = (const float*)d_in[0];
    const int*   amask  = (const int*)  d_in[1];
    const float* W_attn = (const float*)d_in[2];
    const float* b_attn = (const float*)d_in[3];
    const float* W_proj = (const float*)d_in[4];
    const float* b_proj = (const float*)d_in[5];
    float* out = (float*)d_out;

    // 0) preconvert x -> half; transpose weights -> [N][K] half
    preconvert_x<<<(XN4 + 255) / 256, 256>>>(x);
    {
        dim3 g1(N3 / 32, CDIM / 32);
        transpose_w<0, CDIM, N3><<<g1, dim3(32, 8)>>>(W_attn);
        dim3 g2(CDIM / 32, CDIM / 32);
        transpose_w<1, CDIM, CDIM><<<g2, dim3(32, 8)>>>(W_proj);
    }

    const int gemm_smem = 4 * TW * (int)sizeof(uint32_t);   // 2 buf x (A+B)

    // 1) QKV GEMM (fp16 mma) -> half q/k/vT
    {
        cudaFuncSetAttribute(gemm_h<1, CDIM, N3>,
                             cudaFuncAttributeMaxDynamicSharedMemorySize, gemm_smem);
        dim3 grid(N3 / 128, (BATCH * SEQ) / 128);
        gemm_h<1, CDIM, N3><<<grid, 256, gemm_smem>>>(b_attn, nullptr);
    }

    // 2) flash attention (fp16 mma) -> half g_att
    {
        int smem = (2 * KVW + 2 * KVW + BQT * LDF + 128) * (int)sizeof(uint32_t);
        cudaFuncSetAttribute(flash_attn, cudaFuncAttributeMaxDynamicSharedMemorySize, smem);
        dim3 grid(SEQ / BQT, NH, BATCH);
        flash_attn<<<grid, 256, smem>>>(amask);
    }

    // 3) proj GEMM (fp16 mma) -> fp32 out
    {
        cudaFuncSetAttribute(gemm_h<0, CDIM, CDIM>,
                             cudaFuncAttributeMaxDynamicSharedMemorySize, gemm_smem);
        dim3 grid(CDIM / 128, (BATCH * SEQ) / 128);
        gemm_h<0, CDIM, CDIM><<<grid, 256, gemm_smem>>>(b_proj, out);
    }
}

// round 9
// speedup vs baseline: 8.8116x; 1.0370x over previous
#include <cuda_runtime.h>
#include <cuda_fp16.h>
#include <math.h>
#include <stdint.h>

#define BATCH 8
#define SEQ   1024
#define CDIM  768
#define NH    12
#define HD    64
#define N3    (3*CDIM)

// Scratch: fp16 payloads stored in uint32 arrays (guaranteed 4B alignment).
__device__ uint32_t g_q  [BATCH*NH*SEQ*HD/2];   // [B,H,T,D] half, pre-scaled 1/8
__device__ uint32_t g_k  [BATCH*NH*SEQ*HD/2];   // [B,H,T,D] half
__device__ uint32_t g_vT [BATCH*NH*SEQ*HD/2];   // [B,H,D,T] half (transposed!)
__device__ uint32_t g_att[BATCH*SEQ*CDIM/2];    // [B,T,C] half
__device__ uint32_t g_xc [BATCH*SEQ*CDIM/2];    // x in half
__device__ uint32_t g_wat[N3*CDIM/2];           // W_attn^T [N3][CDIM] half
__device__ uint32_t g_wpt[CDIM*CDIM/2];         // W_proj^T [CDIM][CDIM] half

// ---------------------------------------------------------------------------
// helpers
// ---------------------------------------------------------------------------
__device__ __forceinline__ uint32_t f2h2(float a, float b) {
    __half2 h = __floats2half2_rn(a, b);
    return *(uint32_t*)&h;
}

__device__ __forceinline__ void mma_f16(float* c, const uint32_t* a, const uint32_t* b) {
    asm volatile(
        "mma.sync.aligned.m16n8k16.row.col.f32.f16.f16.f32 "
        "{%0,%1,%2,%3}, {%4,%5,%6,%7}, {%8,%9}, {%0,%1,%2,%3};"
        : "+f"(c[0]), "+f"(c[1]), "+f"(c[2]), "+f"(c[3])
        : "r"(a[0]), "r"(a[1]), "r"(a[2]), "r"(a[3]), "r"(b[0]), "r"(b[1]));
}

__device__ __forceinline__ void ldsm4(uint32_t* r, uint32_t a) {
    asm volatile("ldmatrix.sync.aligned.m8n8.x4.shared.b16 {%0,%1,%2,%3}, [%4];"
        : "=r"(r[0]), "=r"(r[1]), "=r"(r[2]), "=r"(r[3]) : "r"(a));
}
__device__ __forceinline__ void ldsm2(uint32_t* r, uint32_t a) {
    asm volatile("ldmatrix.sync.aligned.m8n8.x2.shared.b16 {%0,%1}, [%2];"
        : "=r"(r[0]), "=r"(r[1]) : "r"(a));
}

__device__ __forceinline__ void cpa16(uint32_t saddr, const void* gaddr) {
    asm volatile("cp.async.cg.shared.global [%0], [%1], 16;" :: "r"(saddr), "l"(gaddr));
}
__device__ __forceinline__ void cpa_commit() { asm volatile("cp.async.commit_group;"); }
template<int NN> __device__ __forceinline__ void cpa_wait() {
    asm volatile("cp.async.wait_group %0;" :: "n"(NN));
}
__device__ __forceinline__ uint32_t smem_u32(const void* p) {
    return (uint32_t)__cvta_generic_to_shared(p);
}

// ---------------------------------------------------------------------------
// Preconvert / transpose kernels
// ---------------------------------------------------------------------------
#define XN4 (BATCH*SEQ*CDIM/4)

__global__ void preconvert_x(const float* __restrict__ x)
{
    int i = blockIdx.x * 256 + threadIdx.x;
    if (i < XN4) {
        float4 v = ((const float4*)x)[i];
        uint2 u = { f2h2(v.x, v.y), f2h2(v.z, v.w) };
        ((uint2*)g_xc)[i] = u;
    }
}

// transpose W[K][N] -> Wt[N][K] half. WSEL 0: g_wat, 1: g_wpt.
template<int WSEL, int K, int N>
__global__ void transpose_w(const float* __restrict__ w)
{
    __half* wt = (WSEL == 0) ? (__half*)g_wat : (__half*)g_wpt;
    __shared__ float t[32][33];
    int n0 = blockIdx.x * 32, k0 = blockIdx.y * 32;
    int tx = threadIdx.x, ty = threadIdx.y;   // 32 x 8
    #pragma unroll
    for (int i = 0; i < 32; i += 8)
        t[ty + i][tx] = w[(size_t)(k0 + ty + i) * N + n0 + tx];
    __syncthreads();
    #pragma unroll
    for (int i = 0; i < 32; i += 8)
        wt[(size_t)(n0 + ty + i) * K + k0 + tx] = __float2half(t[tx][ty + i]);
}

// ---------------------------------------------------------------------------
// fp16 tensor-core GEMM: C[M,N] = A[M,K] @ Wt[N,K]^T + bias   (f32 accum)
// BM=128, BN=128, BK=64 halves. 256 threads, 8 warps (2x4), 64x32 per warp.
// Fragments via ldmatrix (x4 for A, x2 for B). smem half2 stride LD2=36.
// MODE 0: A=g_att, W=g_wpt, fp32 out + bias.
// MODE 1: A=g_xc,  W=g_wat, scatter half q(x0.125)/k/vT.
// ---------------------------------------------------------------------------
#define LD2 36
#define TW  (128 * LD2)   // words per tile buffer

template<int MODE, int K, int N>
__global__ __launch_bounds__(256)
void gemm_h(const float* __restrict__ bias, float* __restrict__ Cout)
{
    const uint32_t* A2 = (MODE == 0) ? g_att : g_xc;   // [M][K/2]
    const uint32_t* W2 = (MODE == 0) ? g_wpt : g_wat;  // [N][K/2]
    const int K2 = K / 2;

    extern __shared__ uint32_t sm[];
    uint32_t* As = sm;            // [2][128][LD2]
    uint32_t* Bs = sm + 2 * TW;   // [2][128][LD2]
    const uint32_t sAs = smem_u32(As);
    const uint32_t sBs = smem_u32(Bs);

    const int tid  = threadIdx.x;
    const int bm   = blockIdx.y * 128;
    const int bn   = blockIdx.x * 128;
    const int warp = tid >> 5;
    const int lane = tid & 31;
    const int wm   = warp & 1;
    const int wn   = warp >> 1;
    const int g    = lane >> 2;
    const int t4   = lane & 3;

    // ldmatrix per-lane address components
    const int lr    = lane & 7;
    const int rowAo = wm * 64 + ((lane >> 3) & 1) * 8 + lr;  // + mt*16
    const int colAo = (lane >> 4) * 4;                       // word offset
    const int rowBo = wn * 32 + lr;                          // + nt*8
    const int colBo = ((lane >> 3) & 1) * 4;

    float acc[4][4][4];
    #pragma unroll
    for (int mt = 0; mt < 4; mt++)
        #pragma unroll
        for (int nt = 0; nt < 4; nt++)
            #pragma unroll
            for (int i = 0; i < 4; i++) acc[mt][nt][i] = 0.f;

    const int NC = K / 64;

    auto stage = [&](int buf, int k0w) {   // k0w = k offset in half2 words
        #pragma unroll
        for (int it = 0; it < 4; it++) {
            int i = tid + it * 256;        // 0..1023
            int r = i >> 3, c = i & 7;     // row 0..127, 16B chunk 0..7
            cpa16(sAs + (uint32_t)(buf * TW + r * LD2 + c * 4) * 4,
                  &A2[(size_t)(bm + r) * K2 + k0w + c * 4]);
        }
        #pragma unroll
        for (int it = 0; it < 4; it++) {
            int i = tid + it * 256;
            int r = i >> 3, c = i & 7;
            cpa16(sBs + (uint32_t)(buf * TW + r * LD2 + c * 4) * 4,
                  &W2[(size_t)(bn + r) * K2 + k0w + c * 4]);
        }
        cpa_commit();
    };

    stage(0, 0);
    for (int ck = 0; ck < NC; ck++) {
        int buf = ck & 1;
        if (ck + 1 < NC) { stage(buf ^ 1, (ck + 1) * 32); cpa_wait<1>(); }
        else             { cpa_wait<0>(); }
        __syncthreads();

        const uint32_t bA = sAs + (uint32_t)(buf * TW) * 4;
        const uint32_t bB = sBs + (uint32_t)(buf * TW) * 4;

        #pragma unroll
        for (int ks = 0; ks < 4; ks++) {       // 4 x k16
            const int kk2 = ks * 8;
            uint32_t a[4][4], b[4][2];
            #pragma unroll
            for (int mt = 0; mt < 4; mt++)
                ldsm4(a[mt], bA + (uint32_t)((rowAo + mt * 16) * LD2 + kk2 + colAo) * 4);
            #pragma unroll
            for (int nt = 0; nt < 4; nt++)
                ldsm2(b[nt], bB + (uint32_t)((rowBo + nt * 8) * LD2 + kk2 + colBo) * 4);
            #pragma unroll
            for (int mt = 0; mt < 4; mt++)
                #pragma unroll
                for (int nt = 0; nt < 4; nt++)
                    mma_f16(acc[mt][nt], a[mt], b[nt]);
        }
        __syncthreads();
    }

    // ---- epilogue ----
    #pragma unroll
    for (int mt = 0; mt < 4; mt++) {
        #pragma unroll
        for (int nt = 0; nt < 4; nt++) {
            #pragma unroll
            for (int i = 0; i < 4; i++) {
                int m = bm + wm * 64 + mt * 16 + g + (i >> 1) * 8;
                int n = bn + wn * 32 + nt * 8 + 2 * t4 + (i & 1);
                float v = acc[mt][nt][i] + bias[n];
                if (MODE == 0) {
                    Cout[(size_t)m * N + n] = v;
                } else {
                    int which = n / CDIM;
                    int c = n - which * CDIM;
                    int h = c >> 6;
                    int d = c & 63;
                    int b2 = m >> 10;
                    int t = m & 1023;
                    if (which == 0) {
                        size_t idx = (((size_t)(b2 * NH + h) * SEQ) + t) * HD + d;
                        ((__half*)g_q)[idx] = __float2half(v * 0.125f);
                    } else if (which == 1) {
                        size_t idx = (((size_t)(b2 * NH + h) * SEQ) + t) * HD + d;
                        ((__half*)g_k)[idx] = __float2half(v);
                    } else {
                        size_t idx = (((size_t)(b2 * NH + h) * HD) + d) * SEQ + t;
                        ((__half*)g_vT)[idx] = __float2half(v);
                    }
                }
            }
        }
    }
}

// ---------------------------------------------------------------------------
// Flash attention, fp16 mma + ldmatrix. One block = (b, h, 128 q-rows).
// K tiles [key][d] half2; V tiles from g_vT [d][key] half2; P pane half2.
// ---------------------------------------------------------------------------
#define BQT 128
#define LDF 36            // half2 stride for 64-half rows (Ks/Vs/Ps)
#define KVW (64 * LDF)    // words per K or V buffer

__global__ __launch_bounds__(256)
void flash_attn(const int* __restrict__ mask)
{
    extern __shared__ uint32_t smu[];
    uint32_t* Ks = smu;                       // [2][64][LDF]
    uint32_t* Vs = smu + 2 * KVW;             // [2][64][LDF]
    uint32_t* Ps = Vs + 2 * KVW;              // [128][LDF]   (Q staging, then P)
    float* maskf = (float*)(Ps + BQT * LDF);  // [2][64]
    const uint32_t sKs = smem_u32(Ks);
    const uint32_t sVs = smem_u32(Vs);
    const uint32_t sPs = smem_u32(Ps);

    const int b  = blockIdx.z;
    const int h  = blockIdx.y;
    const int q0 = blockIdx.x * BQT;

    const uint32_t* Qp2 = g_q  + ((size_t)(b * NH + h) * SEQ) * (HD / 2);
    const uint32_t* Kp2 = g_k  + ((size_t)(b * NH + h) * SEQ) * (HD / 2);
    const uint32_t* Vt2 = g_vT + ((size_t)(b * NH + h) * HD) * (SEQ / 2);

    const int tid  = threadIdx.x;
    const int warp = tid >> 5;
    const int lane = tid & 31;
    const int g    = lane >> 2;
    const int t4   = lane & 3;

    // ldmatrix per-lane address components
    const int lr    = lane & 7;
    const int rowAo = warp * 16 + ((lane >> 3) & 1) * 8 + lr;  // A-side (Q/P rows)
    const int colAo = (lane >> 4) * 4;
    const int rowBo = lr;                                      // + nt*8 (K/V rows)
    const int colBo = ((lane >> 3) & 1) * 4;

    auto stage_kv = [&](int buf, int kt) {
        #pragma unroll
        for (int it = 0; it < 2; it++) {
            int i = tid + it * 256;            // 0..511
            int r = i >> 3, c = i & 7;
            cpa16(sKs + (uint32_t)(buf * KVW + r * LDF + c * 4) * 4,
                  &Kp2[(size_t)(kt * 64 + r) * 32 + c * 4]);
        }
        #pragma unroll
        for (int it = 0; it < 2; it++) {
            int i = tid + it * 256;
            int r = i >> 3, c = i & 7;
            cpa16(sVs + (uint32_t)(buf * KVW + r * LDF + c * 4) * 4,
                  &Vt2[(size_t)r * (SEQ / 2) + kt * 32 + c * 4]);
        }
        cpa_commit();
        if (tid < 64)
            maskf[buf * 64 + tid] = (mask[b * SEQ + kt * 64 + tid] == 0) ? -1e30f : 0.f;
    };

    // ---- stage Q (half, pre-scaled) into Ps ----
    #pragma unroll
    for (int it = 0; it < 4; it++) {
        int i = tid + it * 256;               // 0..1023
        int r = i >> 3, c = i & 7;
        cpa16(sPs + (uint32_t)(r * LDF + c * 4) * 4,
              &Qp2[(size_t)(q0 + r) * 32 + c * 4]);
    }
    cpa_commit();
    stage_kv(0, 0);
    cpa_wait<1>();
    __syncthreads();

    uint32_t qf[4][4];
    #pragma unroll
    for (int ks = 0; ks < 4; ks++)
        ldsm4(qf[ks], sPs + (uint32_t)(rowAo * LDF + ks * 8 + colAo) * 4);
    __syncthreads();   // Ps reused as P pane

    float m0v = -1e30f, m1v = -1e30f;
    float l0 = 0.f, l1 = 0.f;
    float oacc[8][4];
    #pragma unroll
    for (int nt = 0; nt < 8; nt++)
        #pragma unroll
        for (int i = 0; i < 4; i++) oacc[nt][i] = 0.f;

    const int NT = SEQ / 64;
    for (int kt = 0; kt < NT; kt++) {
        int buf = kt & 1;
        if (kt + 1 < NT) { stage_kv(buf ^ 1, kt + 1); cpa_wait<1>(); }
        else             { cpa_wait<0>(); }
        __syncthreads();

        const uint32_t bK = sKs + (uint32_t)(buf * KVW) * 4;
        const uint32_t bV = sVs + (uint32_t)(buf * KVW) * 4;
        const float* mb = &maskf[buf * 64];

        // ---- S = Q @ K^T ----
        float sacc[8][4];
        #pragma unroll
        for (int nt = 0; nt < 8; nt++)
            #pragma unroll
            for (int i = 0; i < 4; i++) sacc[nt][i] = 0.f;

        #pragma unroll
        for (int ks = 0; ks < 4; ks++) {
            int kk2 = ks * 8;
            #pragma unroll
            for (int nt = 0; nt < 8; nt++) {
                uint32_t bf[2];
                ldsm2(bf, bK + (uint32_t)((rowBo + nt * 8) * LDF + kk2 + colBo) * 4);
                mma_f16(sacc[nt], qf[ks], bf);
            }
        }

        // ---- mask + online softmax ----
        float tm0 = -1e30f, tm1 = -1e30f;
        #pragma unroll
        for (int nt = 0; nt < 8; nt++) {
            float ma  = mb[nt * 8 + 2 * t4];
            float mb2 = mb[nt * 8 + 2 * t4 + 1];
            sacc[nt][0] += ma; sacc[nt][1] += mb2;
            sacc[nt][2] += ma; sacc[nt][3] += mb2;
            tm0 = fmaxf(tm0, fmaxf(sacc[nt][0], sacc[nt][1]));
            tm1 = fmaxf(tm1, fmaxf(sacc[nt][2], sacc[nt][3]));
        }
        tm0 = fmaxf(tm0, __shfl_xor_sync(0xffffffff, tm0, 1));
        tm0 = fmaxf(tm0, __shfl_xor_sync(0xffffffff, tm0, 2));
        tm1 = fmaxf(tm1, __shfl_xor_sync(0xffffffff, tm1, 1));
        tm1 = fmaxf(tm1, __shfl_xor_sync(0xffffffff, tm1, 2));

        float mn0 = fmaxf(m0v, tm0);
        float mn1 = fmaxf(m1v, tm1);
        float f0 = __expf(m0v - mn0);
        float f1 = __expf(m1v - mn1);
        m0v = mn0; m1v = mn1;
        l0 *= f0; l1 *= f1;
        #pragma unroll
        for (int nt = 0; nt < 8; nt++) {
            oacc[nt][0] *= f0; oacc[nt][1] *= f0;
            oacc[nt][2] *= f1; oacc[nt][3] *= f1;
        }

        int r0 = warp * 16 + g;
        float s0 = 0.f, s1 = 0.f;
        #pragma unroll
        for (int nt = 0; nt < 8; nt++) {
            float e0 = __expf(sacc[nt][0] - mn0);
            float e1 = __expf(sacc[nt][1] - mn0);
            float e2 = __expf(sacc[nt][2] - mn1);
            float e3 = __expf(sacc[nt][3] - mn1);
            s0 += e0 + e1;
            s1 += e2 + e3;
            Ps[(r0)     * LDF + nt * 4 + t4] = f2h2(e0, e1);
            Ps[(r0 + 8) * LDF + nt * 4 + t4] = f2h2(e2, e3);
        }
        s0 += __shfl_xor_sync(0xffffffff, s0, 1);
        s0 += __shfl_xor_sync(0xffffffff, s0, 2);
        s1 += __shfl_xor_sync(0xffffffff, s1, 1);
        s1 += __shfl_xor_sync(0xffffffff, s1, 2);
        l0 += s0; l1 += s1;

        __syncwarp();   // P pane is warp-private

        // ---- O += P @ V ----
        #pragma unroll
        for (int ks = 0; ks < 4; ks++) {
            int kk2 = ks * 8;
            uint32_t af[4];
            ldsm4(af, sPs + (uint32_t)(rowAo * LDF + kk2 + colAo) * 4);
            #pragma unroll
            for (int nt = 0; nt < 8; nt++) {
                uint32_t bf[2];
                ldsm2(bf, bV + (uint32_t)((rowBo + nt * 8) * LDF + kk2 + colBo) * 4);
                mma_f16(oacc[nt], af, bf);
            }
        }
        __syncthreads();
    }

    // ---- epilogue: normalize, write g_att (half2) ----
    {
        float inv0 = 1.f / l0;
        float inv1 = 1.f / l1;
        int r0 = q0 + warp * 16 + g;
        size_t base0 = ((size_t)(b * SEQ + r0))     * (CDIM / 2) + h * (HD / 2);
        size_t base1 = ((size_t)(b * SEQ + r0 + 8)) * (CDIM / 2) + h * (HD / 2);
        #pragma unroll
        for (int nt = 0; nt < 8; nt++) {
            g_att[base0 + nt * 4 + t4] = f2h2(oacc[nt][0] * inv0, oacc[nt][1] * inv0);
            g_att[base1 + nt * 4 + t4] = f2h2(oacc[nt][2] * inv1, oacc[nt][3] * inv1);
        }
    }
}

// ---------------------------------------------------------------------------
extern "C" void kernel_launch(void* const* d_in, const int* in_sizes, int n_in,
                              void* d_out, int out_size)
{
    const float* x      = (const float*)d_in[0];
    const int*   amask  = (const int*)  d_in[1];
    const float* W_attn = (const float*)d_in[2];
    const float* b_attn = (const float*)d_in[3];
    const float* W_proj = (const float*)d_in[4];
    const float* b_proj = (const float*)d_in[5];
    float* out = (float*)d_out;

    // 0) preconvert x -> half; transpose weights -> [N][K] half
    preconvert_x<<<(XN4 + 255) / 256, 256>>>(x);
    {
        dim3 g1(N3 / 32, CDIM / 32);
        transpose_w<0, CDIM, N3><<<g1, dim3(32, 8)>>>(W_attn);
        dim3 g2(CDIM / 32, CDIM / 32);
        transpose_w<1, CDIM, CDIM><<<g2, dim3(32, 8)>>>(W_proj);
    }

    const int gemm_smem = 4 * TW * (int)sizeof(uint32_t);   // 2 buf x (A+B)

    // 1) QKV GEMM (fp16 mma + ldmatrix) -> half q/k/vT
    {
        cudaFuncSetAttribute(gemm_h<1, CDIM, N3>,
                             cudaFuncAttributeMaxDynamicSharedMemorySize, gemm_smem);
        dim3 grid(N3 / 128, (BATCH * SEQ) / 128);
        gemm_h<1, CDIM, N3><<<grid, 256, gemm_smem>>>(b_attn, nullptr);
    }

    // 2) flash attention (fp16 mma + ldmatrix) -> half g_att
    {
        int smem = (2 * KVW + 2 * KVW + BQT * LDF + 128) * (int)sizeof(uint32_t);
        cudaFuncSetAttribute(flash_attn, cudaFuncAttributeMaxDynamicSharedMemorySize, smem);
        dim3 grid(SEQ / BQT, NH, BATCH);
        flash_attn<<<grid, 256, smem>>>(amask);
    }

    // 3) proj GEMM (fp16 mma + ldmatrix) -> fp32 out
    {
        cudaFuncSetAttribute(gemm_h<0, CDIM, CDIM>,
                             cudaFuncAttributeMaxDynamicSharedMemorySize, gemm_smem);
        dim3 grid(CDIM / 128, (BATCH * SEQ) / 128);
        gemm_h<0, CDIM, CDIM><<<grid, 256, gemm_smem>>>(b_proj, out);
    }
}

// round 10
// speedup vs baseline: 9.3293x; 1.0588x over previous
#include <cuda_runtime.h>
#include <cuda_fp16.h>
#include <math.h>
#include <stdint.h>

#define BATCH 8
#define SEQ   1024
#define CDIM  768
#define NH    12
#define HD    64
#define N3    (3*CDIM)

// Scratch: fp16 payloads stored in uint32 arrays (guaranteed 4B alignment).
__device__ uint32_t g_q  [BATCH*NH*SEQ*HD/2];   // [B,H,T,D] half, pre-scaled 1/8
__device__ uint32_t g_k  [BATCH*NH*SEQ*HD/2];   // [B,H,T,D] half
__device__ uint32_t g_vT [BATCH*NH*SEQ*HD/2];   // [B,H,D,T] half (transposed!)
__device__ uint32_t g_att[BATCH*SEQ*CDIM/2];    // [B,T,C] half
__device__ uint32_t g_xc [BATCH*SEQ*CDIM/2];    // x in half
__device__ uint32_t g_wat[N3*CDIM/2];           // W_attn^T [N3][CDIM] half
__device__ uint32_t g_wpt[CDIM*CDIM/2];         // W_proj^T [CDIM][CDIM] half

// ---------------------------------------------------------------------------
// helpers
// ---------------------------------------------------------------------------
__device__ __forceinline__ uint32_t f2h2(float a, float b) {
    __half2 h = __floats2half2_rn(a, b);
    return *(uint32_t*)&h;
}

__device__ __forceinline__ void mma_f16(float* c, const uint32_t* a, const uint32_t* b) {
    asm volatile(
        "mma.sync.aligned.m16n8k16.row.col.f32.f16.f16.f32 "
        "{%0,%1,%2,%3}, {%4,%5,%6,%7}, {%8,%9}, {%0,%1,%2,%3};"
        : "+f"(c[0]), "+f"(c[1]), "+f"(c[2]), "+f"(c[3])
        : "r"(a[0]), "r"(a[1]), "r"(a[2]), "r"(a[3]), "r"(b[0]), "r"(b[1]));
}

__device__ __forceinline__ void ldsm4(uint32_t* r, uint32_t a) {
    asm volatile("ldmatrix.sync.aligned.m8n8.x4.shared.b16 {%0,%1,%2,%3}, [%4];"
        : "=r"(r[0]), "=r"(r[1]), "=r"(r[2]), "=r"(r[3]) : "r"(a));
}
__device__ __forceinline__ void ldsm2(uint32_t* r, uint32_t a) {
    asm volatile("ldmatrix.sync.aligned.m8n8.x2.shared.b16 {%0,%1}, [%2];"
        : "=r"(r[0]), "=r"(r[1]) : "r"(a));
}

__device__ __forceinline__ void cpa16(uint32_t saddr, const void* gaddr) {
    asm volatile("cp.async.cg.shared.global [%0], [%1], 16;" :: "r"(saddr), "l"(gaddr));
}
__device__ __forceinline__ void cpa_commit() { asm volatile("cp.async.commit_group;"); }
template<int NN> __device__ __forceinline__ void cpa_wait() {
    asm volatile("cp.async.wait_group %0;" :: "n"(NN));
}
__device__ __forceinline__ uint32_t smem_u32(const void* p) {
    return (uint32_t)__cvta_generic_to_shared(p);
}

// ---------------------------------------------------------------------------
// Preconvert / transpose kernels
// ---------------------------------------------------------------------------
#define XN4 (BATCH*SEQ*CDIM/4)

__global__ void preconvert_x(const float* __restrict__ x)
{
    int i = blockIdx.x * 256 + threadIdx.x;
    if (i < XN4) {
        float4 v = ((const float4*)x)[i];
        uint2 u = { f2h2(v.x, v.y), f2h2(v.z, v.w) };
        ((uint2*)g_xc)[i] = u;
    }
}

// transpose W[K][N] -> Wt[N][K] half. WSEL 0: g_wat, 1: g_wpt.
template<int WSEL, int K, int N>
__global__ void transpose_w(const float* __restrict__ w)
{
    __half* wt = (WSEL == 0) ? (__half*)g_wat : (__half*)g_wpt;
    __shared__ float t[32][33];
    int n0 = blockIdx.x * 32, k0 = blockIdx.y * 32;
    int tx = threadIdx.x, ty = threadIdx.y;   // 32 x 8
    #pragma unroll
    for (int i = 0; i < 32; i += 8)
        t[ty + i][tx] = w[(size_t)(k0 + ty + i) * N + n0 + tx];
    __syncthreads();
    #pragma unroll
    for (int i = 0; i < 32; i += 8)
        wt[(size_t)(n0 + ty + i) * K + k0 + tx] = __float2half(t[tx][ty + i]);
}

// ---------------------------------------------------------------------------
// fp16 tensor-core GEMM: C[M,N] = A[M,K] @ Wt[N,K]^T + bias   (f32 accum)
// BM=128, BN=128, BK=64 halves. 256 threads, 8 warps (2x4), 64x32 per warp.
// 3-stage cp.async circular pipeline, ONE __syncthreads per chunk.
// MODE 0: A=g_att, W=g_wpt, fp32 out + bias.
// MODE 1: A=g_xc,  W=g_wat, scatter half q(x0.125)/k/vT.
// ---------------------------------------------------------------------------
#define LD2 36
#define TW  (128 * LD2)   // words per tile buffer
#define GST 3             // pipeline stages

template<int MODE, int K, int N>
__global__ __launch_bounds__(256)
void gemm_h(const float* __restrict__ bias, float* __restrict__ Cout)
{
    const uint32_t* A2 = (MODE == 0) ? g_att : g_xc;   // [M][K/2]
    const uint32_t* W2 = (MODE == 0) ? g_wpt : g_wat;  // [N][K/2]
    const int K2 = K / 2;

    extern __shared__ uint32_t sm[];
    uint32_t* As = sm;              // [GST][128][LD2]
    uint32_t* Bs = sm + GST * TW;   // [GST][128][LD2]
    const uint32_t sAs = smem_u32(As);
    const uint32_t sBs = smem_u32(Bs);

    const int tid  = threadIdx.x;
    const int bm   = blockIdx.y * 128;
    const int bn   = blockIdx.x * 128;
    const int warp = tid >> 5;
    const int lane = tid & 31;
    const int wm   = warp & 1;
    const int wn   = warp >> 1;
    const int g    = lane >> 2;
    const int t4   = lane & 3;

    // ldmatrix per-lane address components
    const int lr    = lane & 7;
    const int rowAo = wm * 64 + ((lane >> 3) & 1) * 8 + lr;  // + mt*16
    const int colAo = (lane >> 4) * 4;                       // word offset
    const int rowBo = wn * 32 + lr;                          // + nt*8
    const int colBo = ((lane >> 3) & 1) * 4;

    float acc[4][4][4];
    #pragma unroll
    for (int mt = 0; mt < 4; mt++)
        #pragma unroll
        for (int nt = 0; nt < 4; nt++)
            #pragma unroll
            for (int i = 0; i < 4; i++) acc[mt][nt][i] = 0.f;

    const int NC = K / 64;

    auto stage = [&](int buf, int k0w) {   // k0w = k offset in half2 words
        #pragma unroll
        for (int it = 0; it < 4; it++) {
            int i = tid + it * 256;        // 0..1023
            int r = i >> 3, c = i & 7;     // row 0..127, 16B chunk 0..7
            cpa16(sAs + (uint32_t)(buf * TW + r * LD2 + c * 4) * 4,
                  &A2[(size_t)(bm + r) * K2 + k0w + c * 4]);
        }
        #pragma unroll
        for (int it = 0; it < 4; it++) {
            int i = tid + it * 256;
            int r = i >> 3, c = i & 7;
            cpa16(sBs + (uint32_t)(buf * TW + r * LD2 + c * 4) * 4,
                  &W2[(size_t)(bn + r) * K2 + k0w + c * 4]);
        }
        cpa_commit();
    };

    // prologue: 2 stages in flight
    stage(0, 0);
    stage(1, 32);

    int buf = 0;
    for (int ck = 0; ck < NC; ck++) {
        cpa_wait<1>();        // buffer `buf` complete (>=2 commits ahead)
        __syncthreads();      // all warps done computing buffer (buf+1)%GST's prior life

        if (ck + 2 < NC) {
            int nbuf = buf + 2; if (nbuf >= GST) nbuf -= GST;
            stage(nbuf, (ck + 2) * 32);
        }

        const uint32_t bA = sAs + (uint32_t)(buf * TW) * 4;
        const uint32_t bB = sBs + (uint32_t)(buf * TW) * 4;

        #pragma unroll
        for (int ks = 0; ks < 4; ks++) {       // 4 x k16
            const int kk2 = ks * 8;
            uint32_t a[4][4], b[4][2];
            #pragma unroll
            for (int mt = 0; mt < 4; mt++)
                ldsm4(a[mt], bA + (uint32_t)((rowAo + mt * 16) * LD2 + kk2 + colAo) * 4);
            #pragma unroll
            for (int nt = 0; nt < 4; nt++)
                ldsm2(b[nt], bB + (uint32_t)((rowBo + nt * 8) * LD2 + kk2 + colBo) * 4);
            #pragma unroll
            for (int mt = 0; mt < 4; mt++)
                #pragma unroll
                for (int nt = 0; nt < 4; nt++)
                    mma_f16(acc[mt][nt], a[mt], b[nt]);
        }

        buf++; if (buf >= GST) buf = 0;
    }

    // ---- epilogue ----
    #pragma unroll
    for (int mt = 0; mt < 4; mt++) {
        #pragma unroll
        for (int nt = 0; nt < 4; nt++) {
            #pragma unroll
            for (int i = 0; i < 4; i++) {
                int m = bm + wm * 64 + mt * 16 + g + (i >> 1) * 8;
                int n = bn + wn * 32 + nt * 8 + 2 * t4 + (i & 1);
                float v = acc[mt][nt][i] + bias[n];
                if (MODE == 0) {
                    Cout[(size_t)m * N + n] = v;
                } else {
                    int which = n / CDIM;
                    int c = n - which * CDIM;
                    int h = c >> 6;
                    int d = c & 63;
                    int b2 = m >> 10;
                    int t = m & 1023;
                    if (which == 0) {
                        size_t idx = (((size_t)(b2 * NH + h) * SEQ) + t) * HD + d;
                        ((__half*)g_q)[idx] = __float2half(v * 0.125f);
                    } else if (which == 1) {
                        size_t idx = (((size_t)(b2 * NH + h) * SEQ) + t) * HD + d;
                        ((__half*)g_k)[idx] = __float2half(v);
                    } else {
                        size_t idx = (((size_t)(b2 * NH + h) * HD) + d) * SEQ + t;
                        ((__half*)g_vT)[idx] = __float2half(v);
                    }
                }
            }
        }
    }
}

// ---------------------------------------------------------------------------
// Flash attention, fp16 mma + ldmatrix, 3-stage K/V pipeline, 1 sync/iter.
// One block = (b, h, 128 q-rows). K tiles [key][d]; V from g_vT [d][key].
// ---------------------------------------------------------------------------
#define BQT 128
#define LDF 36            // half2 stride for 64-half rows (Ks/Vs/Ps)
#define KVW (64 * LDF)    // words per K or V buffer
#define FST 3

__global__ __launch_bounds__(256)
void flash_attn(const int* __restrict__ mask)
{
    extern __shared__ uint32_t smu[];
    uint32_t* Ks = smu;                        // [FST][64][LDF]
    uint32_t* Vs = smu + FST * KVW;            // [FST][64][LDF]
    uint32_t* Ps = Vs + FST * KVW;             // [128][LDF]   (Q staging, then P)
    float* maskf = (float*)(Ps + BQT * LDF);   // [FST][64]
    const uint32_t sKs = smem_u32(Ks);
    const uint32_t sVs = smem_u32(Vs);
    const uint32_t sPs = smem_u32(Ps);

    const int b  = blockIdx.z;
    const int h  = blockIdx.y;
    const int q0 = blockIdx.x * BQT;

    const uint32_t* Qp2 = g_q  + ((size_t)(b * NH + h) * SEQ) * (HD / 2);
    const uint32_t* Kp2 = g_k  + ((size_t)(b * NH + h) * SEQ) * (HD / 2);
    const uint32_t* Vt2 = g_vT + ((size_t)(b * NH + h) * HD) * (SEQ / 2);

    const int tid  = threadIdx.x;
    const int warp = tid >> 5;
    const int lane = tid & 31;
    const int g    = lane >> 2;
    const int t4   = lane & 3;

    // ldmatrix per-lane address components
    const int lr    = lane & 7;
    const int rowAo = warp * 16 + ((lane >> 3) & 1) * 8 + lr;  // A-side (Q/P rows)
    const int colAo = (lane >> 4) * 4;
    const int rowBo = lr;                                      // + nt*8 (K/V rows)
    const int colBo = ((lane >> 3) & 1) * 4;

    auto stage_kv = [&](int buf, int kt) {
        #pragma unroll
        for (int it = 0; it < 2; it++) {
            int i = tid + it * 256;            // 0..511
            int r = i >> 3, c = i & 7;
            cpa16(sKs + (uint32_t)(buf * KVW + r * LDF + c * 4) * 4,
                  &Kp2[(size_t)(kt * 64 + r) * 32 + c * 4]);
        }
        #pragma unroll
        for (int it = 0; it < 2; it++) {
            int i = tid + it * 256;
            int r = i >> 3, c = i & 7;
            cpa16(sVs + (uint32_t)(buf * KVW + r * LDF + c * 4) * 4,
                  &Vt2[(size_t)r * (SEQ / 2) + kt * 32 + c * 4]);
        }
        cpa_commit();
        if (tid < 64)
            maskf[buf * 64 + tid] = (mask[b * SEQ + kt * 64 + tid] == 0) ? -1e30f : 0.f;
    };

    // ---- prologue: stage Q, then kv0, kv1 ----
    #pragma unroll
    for (int it = 0; it < 4; it++) {
        int i = tid + it * 256;               // 0..1023
        int r = i >> 3, c = i & 7;
        cpa16(sPs + (uint32_t)(r * LDF + c * 4) * 4,
              &Qp2[(size_t)(q0 + r) * 32 + c * 4]);
    }
    cpa_commit();
    stage_kv(0, 0);
    stage_kv(1, 1);
    cpa_wait<2>();     // Q group complete
    __syncthreads();

    uint32_t qf[4][4];
    #pragma unroll
    for (int ks = 0; ks < 4; ks++)
        ldsm4(qf[ks], sPs + (uint32_t)(rowAo * LDF + ks * 8 + colAo) * 4);
    __syncthreads();   // Ps reused as P pane

    float m0v = -1e30f, m1v = -1e30f;
    float l0 = 0.f, l1 = 0.f;
    float oacc[8][4];
    #pragma unroll
    for (int nt = 0; nt < 8; nt++)
        #pragma unroll
        for (int i = 0; i < 4; i++) oacc[nt][i] = 0.f;

    const int NT = SEQ / 64;
    int buf = 0;
    for (int kt = 0; kt < NT; kt++) {
        cpa_wait<1>();     // buffer `buf` ready
        __syncthreads();   // all warps done with buffer (buf+1)%FST's prior life

        if (kt + 2 < NT) {
            int nbuf = buf + 2; if (nbuf >= FST) nbuf -= FST;
            stage_kv(nbuf, kt + 2);
        }

        const uint32_t bK = sKs + (uint32_t)(buf * KVW) * 4;
        const uint32_t bV = sVs + (uint32_t)(buf * KVW) * 4;
        const float* mb = &maskf[buf * 64];

        // ---- S = Q @ K^T ----
        float sacc[8][4];
        #pragma unroll
        for (int nt = 0; nt < 8; nt++)
            #pragma unroll
            for (int i = 0; i < 4; i++) sacc[nt][i] = 0.f;

        #pragma unroll
        for (int ks = 0; ks < 4; ks++) {
            int kk2 = ks * 8;
            #pragma unroll
            for (int nt = 0; nt < 8; nt++) {
                uint32_t bf[2];
                ldsm2(bf, bK + (uint32_t)((rowBo + nt * 8) * LDF + kk2 + colBo) * 4);
                mma_f16(sacc[nt], qf[ks], bf);
            }
        }

        // ---- mask + online softmax ----
        float tm0 = -1e30f, tm1 = -1e30f;
        #pragma unroll
        for (int nt = 0; nt < 8; nt++) {
            float ma  = mb[nt * 8 + 2 * t4];
            float mb2 = mb[nt * 8 + 2 * t4 + 1];
            sacc[nt][0] += ma; sacc[nt][1] += mb2;
            sacc[nt][2] += ma; sacc[nt][3] += mb2;
            tm0 = fmaxf(tm0, fmaxf(sacc[nt][0], sacc[nt][1]));
            tm1 = fmaxf(tm1, fmaxf(sacc[nt][2], sacc[nt][3]));
        }
        tm0 = fmaxf(tm0, __shfl_xor_sync(0xffffffff, tm0, 1));
        tm0 = fmaxf(tm0, __shfl_xor_sync(0xffffffff, tm0, 2));
        tm1 = fmaxf(tm1, __shfl_xor_sync(0xffffffff, tm1, 1));
        tm1 = fmaxf(tm1, __shfl_xor_sync(0xffffffff, tm1, 2));

        float mn0 = fmaxf(m0v, tm0);
        float mn1 = fmaxf(m1v, tm1);
        float f0 = __expf(m0v - mn0);
        float f1 = __expf(m1v - mn1);
        m0v = mn0; m1v = mn1;
        l0 *= f0; l1 *= f1;
        #pragma unroll
        for (int nt = 0; nt < 8; nt++) {
            oacc[nt][0] *= f0; oacc[nt][1] *= f0;
            oacc[nt][2] *= f1; oacc[nt][3] *= f1;
        }

        int r0 = warp * 16 + g;
        float s0 = 0.f, s1 = 0.f;
        #pragma unroll
        for (int nt = 0; nt < 8; nt++) {
            float e0 = __expf(sacc[nt][0] - mn0);
            float e1 = __expf(sacc[nt][1] - mn0);
            float e2 = __expf(sacc[nt][2] - mn1);
            float e3 = __expf(sacc[nt][3] - mn1);
            s0 += e0 + e1;
            s1 += e2 + e3;
            Ps[(r0)     * LDF + nt * 4 + t4] = f2h2(e0, e1);
            Ps[(r0 + 8) * LDF + nt * 4 + t4] = f2h2(e2, e3);
        }
        s0 += __shfl_xor_sync(0xffffffff, s0, 1);
        s0 += __shfl_xor_sync(0xffffffff, s0, 2);
        s1 += __shfl_xor_sync(0xffffffff, s1, 1);
        s1 += __shfl_xor_sync(0xffffffff, s1, 2);
        l0 += s0; l1 += s1;

        __syncwarp();   // P pane is warp-private

        // ---- O += P @ V ----
        #pragma unroll
        for (int ks = 0; ks < 4; ks++) {
            int kk2 = ks * 8;
            uint32_t af[4];
            ldsm4(af, sPs + (uint32_t)(rowAo * LDF + kk2 + colAo) * 4);
            #pragma unroll
            for (int nt = 0; nt < 8; nt++) {
                uint32_t bf[2];
                ldsm2(bf, bV + (uint32_t)((rowBo + nt * 8) * LDF + kk2 + colBo) * 4);
                mma_f16(oacc[nt], af, bf);
            }
        }

        buf++; if (buf >= FST) buf = 0;
    }

    // ---- epilogue: normalize, write g_att (half2) ----
    {
        float inv0 = 1.f / l0;
        float inv1 = 1.f / l1;
        int r0 = q0 + warp * 16 + g;
        size_t base0 = ((size_t)(b * SEQ + r0))     * (CDIM / 2) + h * (HD / 2);
        size_t base1 = ((size_t)(b * SEQ + r0 + 8)) * (CDIM / 2) + h * (HD / 2);
        #pragma unroll
        for (int nt = 0; nt < 8; nt++) {
            g_att[base0 + nt * 4 + t4] = f2h2(oacc[nt][0] * inv0, oacc[nt][1] * inv0);
            g_att[base1 + nt * 4 + t4] = f2h2(oacc[nt][2] * inv1, oacc[nt][3] * inv1);
        }
    }
}

// ---------------------------------------------------------------------------
extern "C" void kernel_launch(void* const* d_in, const int* in_sizes, int n_in,
                              void* d_out, int out_size)
{
    const float* x      = (const float*)d_in[0];
    const int*   amask  = (const int*)  d_in[1];
    const float* W_attn = (const float*)d_in[2];
    const float* b_attn = (const float*)d_in[3];
    const float* W_proj = (const float*)d_in[4];
    const float* b_proj = (const float*)d_in[5];
    float* out = (float*)d_out;

    // 0) preconvert x -> half; transpose weights -> [N][K] half
    preconvert_x<<<(XN4 + 255) / 256, 256>>>(x);
    {
        dim3 g1(N3 / 32, CDIM / 32);
        transpose_w<0, CDIM, N3><<<g1, dim3(32, 8)>>>(W_attn);
        dim3 g2(CDIM / 32, CDIM / 32);
        transpose_w<1, CDIM, CDIM><<<g2, dim3(32, 8)>>>(W_proj);
    }

    const int gemm_smem = 2 * GST * TW * (int)sizeof(uint32_t);   // GST x (A+B)

    // 1) QKV GEMM (fp16 mma + ldmatrix, 3-stage) -> half q/k/vT
    {
        cudaFuncSetAttribute(gemm_h<1, CDIM, N3>,
                             cudaFuncAttributeMaxDynamicSharedMemorySize, gemm_smem);
        dim3 grid(N3 / 128, (BATCH * SEQ) / 128);
        gemm_h<1, CDIM, N3><<<grid, 256, gemm_smem>>>(b_attn, nullptr);
    }

    // 2) flash attention (fp16 mma + ldmatrix, 3-stage) -> half g_att
    {
        int smem = (2 * FST * KVW + BQT * LDF + FST * 64 + 64) * (int)sizeof(uint32_t);
        cudaFuncSetAttribute(flash_attn, cudaFuncAttributeMaxDynamicSharedMemorySize, smem);
        dim3 grid(SEQ / BQT, NH, BATCH);
        flash_attn<<<grid, 256, smem>>>(amask);
    }

    // 3) proj GEMM (fp16 mma + ldmatrix, 3-stage) -> fp32 out
    {
        cudaFuncSetAttribute(gemm_h<0, CDIM, CDIM>,
                             cudaFuncAttributeMaxDynamicSharedMemorySize, gemm_smem);
        dim3 grid(CDIM / 128, (BATCH * SEQ) / 128);
        gemm_h<0, CDIM, CDIM><<<grid, 256, gemm_smem>>>(b_proj, out);
    }
}

// round 11
// speedup vs baseline: 9.4727x; 1.0154x over previous
#include <cuda_runtime.h>
#include <cuda_fp16.h>
#include <math.h>
#include <stdint.h>

#define BATCH 8
#define SEQ   1024
#define CDIM  768
#define NH    12
#define HD    64
#define N3    (3*CDIM)

// Scratch: fp16 payloads stored in uint32 arrays (guaranteed 4B alignment).
__device__ uint32_t g_q  [BATCH*NH*SEQ*HD/2];   // [B,H,T,D] half, pre-scaled 1/8
__device__ uint32_t g_k  [BATCH*NH*SEQ*HD/2];   // [B,H,T,D] half
__device__ uint32_t g_vT [BATCH*NH*SEQ*HD/2];   // [B,H,D,T] half (transposed!)
__device__ uint32_t g_att[BATCH*SEQ*CDIM/2];    // [B,T,C] half
__device__ uint32_t g_xc [BATCH*SEQ*CDIM/2];    // x in half
__device__ uint32_t g_wat[N3*CDIM/2];           // W_attn^T [N3][CDIM] half
__device__ uint32_t g_wpt[CDIM*CDIM/2];         // W_proj^T [CDIM][CDIM] half

// ---------------------------------------------------------------------------
// helpers
// ---------------------------------------------------------------------------
__device__ __forceinline__ uint32_t f2h2(float a, float b) {
    __half2 h = __floats2half2_rn(a, b);
    return *(uint32_t*)&h;
}

__device__ __forceinline__ void mma_f16(float* c, const uint32_t* a, const uint32_t* b) {
    asm volatile(
        "mma.sync.aligned.m16n8k16.row.col.f32.f16.f16.f32 "
        "{%0,%1,%2,%3}, {%4,%5,%6,%7}, {%8,%9}, {%0,%1,%2,%3};"
        : "+f"(c[0]), "+f"(c[1]), "+f"(c[2]), "+f"(c[3])
        : "r"(a[0]), "r"(a[1]), "r"(a[2]), "r"(a[3]), "r"(b[0]), "r"(b[1]));
}

__device__ __forceinline__ void ldsm4(uint32_t* r, uint32_t a) {
    asm volatile("ldmatrix.sync.aligned.m8n8.x4.shared.b16 {%0,%1,%2,%3}, [%4];"
        : "=r"(r[0]), "=r"(r[1]), "=r"(r[2]), "=r"(r[3]) : "r"(a));
}

__device__ __forceinline__ void cpa16(uint32_t saddr, const void* gaddr) {
    asm volatile("cp.async.cg.shared.global [%0], [%1], 16;" :: "r"(saddr), "l"(gaddr));
}
__device__ __forceinline__ void cpa_commit() { asm volatile("cp.async.commit_group;"); }
template<int NN> __device__ __forceinline__ void cpa_wait() {
    asm volatile("cp.async.wait_group %0;" :: "n"(NN));
}
__device__ __forceinline__ uint32_t smem_u32(const void* p) {
    return (uint32_t)__cvta_generic_to_shared(p);
}

// ---------------------------------------------------------------------------
// Preconvert / transpose kernels
// ---------------------------------------------------------------------------
#define XN4 (BATCH*SEQ*CDIM/4)

__global__ void preconvert_x(const float* __restrict__ x)
{
    int i = blockIdx.x * 256 + threadIdx.x;
    if (i < XN4) {
        float4 v = ((const float4*)x)[i];
        uint2 u = { f2h2(v.x, v.y), f2h2(v.z, v.w) };
        ((uint2*)g_xc)[i] = u;
    }
}

// transpose W[K][N] -> Wt[N][K] half. WSEL 0: g_wat, 1: g_wpt.
template<int WSEL, int K, int N>
__global__ void transpose_w(const float* __restrict__ w)
{
    __half* wt = (WSEL == 0) ? (__half*)g_wat : (__half*)g_wpt;
    __shared__ float t[32][33];
    int n0 = blockIdx.x * 32, k0 = blockIdx.y * 32;
    int tx = threadIdx.x, ty = threadIdx.y;   // 32 x 8
    #pragma unroll
    for (int i = 0; i < 32; i += 8)
        t[ty + i][tx] = w[(size_t)(k0 + ty + i) * N + n0 + tx];
    __syncthreads();
    #pragma unroll
    for (int i = 0; i < 32; i += 8)
        wt[(size_t)(n0 + ty + i) * K + k0 + tx] = __float2half(t[tx][ty + i]);
}

// ---------------------------------------------------------------------------
// fp16 tensor-core GEMM: C[M,N] = A[M,K] @ Wt[N,K]^T + bias   (f32 accum)
// BM=128, BN=128, BK=64 halves. 256 threads, 8 warps (2x4), 64x32 per warp.
// 3-stage cp.async circular pipeline, ONE __syncthreads per chunk.
// Fragment sets double-buffered across ks (hides LDS latency behind mma).
// MODE 0: A=g_att, W=g_wpt, fp32 out + bias.
// MODE 1: A=g_xc,  W=g_wat, scatter half q(x0.125)/k/vT.
// ---------------------------------------------------------------------------
#define LD2 36
#define TW  (128 * LD2)   // words per tile buffer
#define GST 3             // pipeline stages

template<int MODE, int K, int N>
__global__ __launch_bounds__(256, 2)
void gemm_h(const float* __restrict__ bias, float* __restrict__ Cout)
{
    const uint32_t* A2 = (MODE == 0) ? g_att : g_xc;   // [M][K/2]
    const uint32_t* W2 = (MODE == 0) ? g_wpt : g_wat;  // [N][K/2]
    const int K2 = K / 2;

    extern __shared__ uint32_t sm[];
    uint32_t* As = sm;              // [GST][128][LD2]
    uint32_t* Bs = sm + GST * TW;   // [GST][128][LD2]
    const uint32_t sAs = smem_u32(As);
    const uint32_t sBs = smem_u32(Bs);

    const int tid  = threadIdx.x;
    const int bm   = blockIdx.y * 128;
    const int bn   = blockIdx.x * 128;
    const int warp = tid >> 5;
    const int lane = tid & 31;
    const int wm   = warp & 1;
    const int wn   = warp >> 1;
    const int g    = lane >> 2;
    const int t4   = lane & 3;

    // ldmatrix per-lane address components
    const int lr    = lane & 7;
    const int rowAo = wm * 64 + ((lane >> 3) & 1) * 8 + lr;  // + mt*16
    const int colAo = (lane >> 4) * 4;                       // word offset
    // paired-B ldsm4: mats = (n0-7,k0),(n0-7,k8),(n8-15,k0),(n8-15,k8)
    const int rowB4 = wn * 32 + lr + ((lane >> 4) & 1) * 8;  // + nt2*16
    const int colB4 = ((lane >> 3) & 1) * 4;

    float acc[4][4][4];
    #pragma unroll
    for (int mt = 0; mt < 4; mt++)
        #pragma unroll
        for (int nt = 0; nt < 4; nt++)
            #pragma unroll
            for (int i = 0; i < 4; i++) acc[mt][nt][i] = 0.f;

    const int NC = K / 64;

    auto stage = [&](int buf, int k0w) {   // k0w = k offset in half2 words
        #pragma unroll
        for (int it = 0; it < 4; it++) {
            int i = tid + it * 256;        // 0..1023
            int r = i >> 3, c = i & 7;     // row 0..127, 16B chunk 0..7
            cpa16(sAs + (uint32_t)(buf * TW + r * LD2 + c * 4) * 4,
                  &A2[(size_t)(bm + r) * K2 + k0w + c * 4]);
        }
        #pragma unroll
        for (int it = 0; it < 4; it++) {
            int i = tid + it * 256;
            int r = i >> 3, c = i & 7;
            cpa16(sBs + (uint32_t)(buf * TW + r * LD2 + c * 4) * 4,
                  &W2[(size_t)(bn + r) * K2 + k0w + c * 4]);
        }
        cpa_commit();
    };

    // prologue: 2 stages in flight
    stage(0, 0);
    stage(1, 32);

    int buf = 0;
    for (int ck = 0; ck < NC; ck++) {
        cpa_wait<1>();        // buffer `buf` complete (>=2 commits ahead)
        __syncthreads();      // all warps done computing buffer (buf+1)%GST's prior life

        if (ck + 2 < NC) {
            int nbuf = buf + 2; if (nbuf >= GST) nbuf -= GST;
            stage(nbuf, (ck + 2) * 32);
        }

        const uint32_t bA = sAs + (uint32_t)(buf * TW) * 4;
        const uint32_t bB = sBs + (uint32_t)(buf * TW) * 4;

        uint32_t a[2][4][4], b[2][2][4];
        // load ks=0 fragments
        #pragma unroll
        for (int mt = 0; mt < 4; mt++)
            ldsm4(a[0][mt], bA + (uint32_t)((rowAo + mt * 16) * LD2 + colAo) * 4);
        #pragma unroll
        for (int nt2 = 0; nt2 < 2; nt2++)
            ldsm4(b[0][nt2], bB + (uint32_t)((rowB4 + nt2 * 16) * LD2 + colB4) * 4);

        #pragma unroll
        for (int ks = 0; ks < 4; ks++) {
            const int cur = ks & 1;
            if (ks < 3) {
                const int kk2n = (ks + 1) * 8;
                #pragma unroll
                for (int mt = 0; mt < 4; mt++)
                    ldsm4(a[cur ^ 1][mt],
                          bA + (uint32_t)((rowAo + mt * 16) * LD2 + kk2n + colAo) * 4);
                #pragma unroll
                for (int nt2 = 0; nt2 < 2; nt2++)
                    ldsm4(b[cur ^ 1][nt2],
                          bB + (uint32_t)((rowB4 + nt2 * 16) * LD2 + kk2n + colB4) * 4);
            }
            #pragma unroll
            for (int mt = 0; mt < 4; mt++)
                #pragma unroll
                for (int nt = 0; nt < 4; nt++)
                    mma_f16(acc[mt][nt], a[cur][mt], &b[cur][nt >> 1][(nt & 1) * 2]);
        }

        buf++; if (buf >= GST) buf = 0;
    }

    // ---- epilogue ----
    #pragma unroll
    for (int mt = 0; mt < 4; mt++) {
        #pragma unroll
        for (int nt = 0; nt < 4; nt++) {
            #pragma unroll
            for (int i = 0; i < 4; i++) {
                int m = bm + wm * 64 + mt * 16 + g + (i >> 1) * 8;
                int n = bn + wn * 32 + nt * 8 + 2 * t4 + (i & 1);
                float v = acc[mt][nt][i] + bias[n];
                if (MODE == 0) {
                    Cout[(size_t)m * N + n] = v;
                } else {
                    int which = n / CDIM;
                    int c = n - which * CDIM;
                    int h = c >> 6;
                    int d = c & 63;
                    int b2 = m >> 10;
                    int t = m & 1023;
                    if (which == 0) {
                        size_t idx = (((size_t)(b2 * NH + h) * SEQ) + t) * HD + d;
                        ((__half*)g_q)[idx] = __float2half(v * 0.125f);
                    } else if (which == 1) {
                        size_t idx = (((size_t)(b2 * NH + h) * SEQ) + t) * HD + d;
                        ((__half*)g_k)[idx] = __float2half(v);
                    } else {
                        size_t idx = (((size_t)(b2 * NH + h) * HD) + d) * SEQ + t;
                        ((__half*)g_vT)[idx] = __float2half(v);
                    }
                }
            }
        }
    }
}

// ---------------------------------------------------------------------------
// Flash attention, fp16 mma + ldmatrix, 3-stage K/V pipeline, 1 sync/iter,
// fragment sets double-buffered across ks in both mma loops.
// One block = (b, h, 128 q-rows). K tiles [key][d]; V from g_vT [d][key].
// ---------------------------------------------------------------------------
#define BQT 128
#define LDF 36            // half2 stride for 64-half rows (Ks/Vs/Ps)
#define KVW (64 * LDF)    // words per K or V buffer
#define FST 3

__global__ __launch_bounds__(256, 2)
void flash_attn(const int* __restrict__ mask)
{
    extern __shared__ uint32_t smu[];
    uint32_t* Ks = smu;                        // [FST][64][LDF]
    uint32_t* Vs = smu + FST * KVW;            // [FST][64][LDF]
    uint32_t* Ps = Vs + FST * KVW;             // [128][LDF]   (Q staging, then P)
    float* maskf = (float*)(Ps + BQT * LDF);   // [FST][64]
    const uint32_t sKs = smem_u32(Ks);
    const uint32_t sVs = smem_u32(Vs);
    const uint32_t sPs = smem_u32(Ps);

    const int b  = blockIdx.z;
    const int h  = blockIdx.y;
    const int q0 = blockIdx.x * BQT;

    const uint32_t* Qp2 = g_q  + ((size_t)(b * NH + h) * SEQ) * (HD / 2);
    const uint32_t* Kp2 = g_k  + ((size_t)(b * NH + h) * SEQ) * (HD / 2);
    const uint32_t* Vt2 = g_vT + ((size_t)(b * NH + h) * HD) * (SEQ / 2);

    const int tid  = threadIdx.x;
    const int warp = tid >> 5;
    const int lane = tid & 31;
    const int g    = lane >> 2;
    const int t4   = lane & 3;

    // ldmatrix per-lane address components
    const int lr    = lane & 7;
    const int rowAo = warp * 16 + ((lane >> 3) & 1) * 8 + lr;  // A-side (Q/P rows)
    const int colAo = (lane >> 4) * 4;
    // paired-B ldsm4 for K/V rows (+ nt2*16)
    const int rowB4 = lr + ((lane >> 4) & 1) * 8;
    const int colB4 = ((lane >> 3) & 1) * 4;

    auto stage_kv = [&](int buf, int kt) {
        #pragma unroll
        for (int it = 0; it < 2; it++) {
            int i = tid + it * 256;            // 0..511
            int r = i >> 3, c = i & 7;
            cpa16(sKs + (uint32_t)(buf * KVW + r * LDF + c * 4) * 4,
                  &Kp2[(size_t)(kt * 64 + r) * 32 + c * 4]);
        }
        #pragma unroll
        for (int it = 0; it < 2; it++) {
            int i = tid + it * 256;
            int r = i >> 3, c = i & 7;
            cpa16(sVs + (uint32_t)(buf * KVW + r * LDF + c * 4) * 4,
                  &Vt2[(size_t)r * (SEQ / 2) + kt * 32 + c * 4]);
        }
        cpa_commit();
        if (tid < 64)
            maskf[buf * 64 + tid] = (mask[b * SEQ + kt * 64 + tid] == 0) ? -1e30f : 0.f;
    };

    // ---- prologue: stage Q, then kv0, kv1 ----
    #pragma unroll
    for (int it = 0; it < 4; it++) {
        int i = tid + it * 256;               // 0..1023
        int r = i >> 3, c = i & 7;
        cpa16(sPs + (uint32_t)(r * LDF + c * 4) * 4,
              &Qp2[(size_t)(q0 + r) * 32 + c * 4]);
    }
    cpa_commit();
    stage_kv(0, 0);
    stage_kv(1, 1);
    cpa_wait<2>();     // Q group complete
    __syncthreads();

    uint32_t qf[4][4];
    #pragma unroll
    for (int ks = 0; ks < 4; ks++)
        ldsm4(qf[ks], sPs + (uint32_t)(rowAo * LDF + ks * 8 + colAo) * 4);
    __syncthreads();   // Ps reused as P pane

    float m0v = -1e30f, m1v = -1e30f;
    float l0 = 0.f, l1 = 0.f;
    float oacc[8][4];
    #pragma unroll
    for (int nt = 0; nt < 8; nt++)
        #pragma unroll
        for (int i = 0; i < 4; i++) oacc[nt][i] = 0.f;

    const int NT = SEQ / 64;
    int buf = 0;
    for (int kt = 0; kt < NT; kt++) {
        cpa_wait<1>();     // buffer `buf` ready
        __syncthreads();   // all warps done with buffer (buf+1)%FST's prior life

        if (kt + 2 < NT) {
            int nbuf = buf + 2; if (nbuf >= FST) nbuf -= FST;
            stage_kv(nbuf, kt + 2);
        }

        const uint32_t bK = sKs + (uint32_t)(buf * KVW) * 4;
        const uint32_t bV = sVs + (uint32_t)(buf * KVW) * 4;
        const float* mb = &maskf[buf * 64];

        // ---- S = Q @ K^T  (K-fragments double-buffered across ks) ----
        float sacc[8][4];
        #pragma unroll
        for (int nt = 0; nt < 8; nt++)
            #pragma unroll
            for (int i = 0; i < 4; i++) sacc[nt][i] = 0.f;

        {
            uint32_t kb[2][4][4];
            #pragma unroll
            for (int nt2 = 0; nt2 < 4; nt2++)
                ldsm4(kb[0][nt2], bK + (uint32_t)((rowB4 + nt2 * 16) * LDF + colB4) * 4);

            #pragma unroll
            for (int ks = 0; ks < 4; ks++) {
                const int cur = ks & 1;
                if (ks < 3) {
                    const int kk2n = (ks + 1) * 8;
                    #pragma unroll
                    for (int nt2 = 0; nt2 < 4; nt2++)
                        ldsm4(kb[cur ^ 1][nt2],
                              bK + (uint32_t)((rowB4 + nt2 * 16) * LDF + kk2n + colB4) * 4);
                }
                #pragma unroll
                for (int nt = 0; nt < 8; nt++)
                    mma_f16(sacc[nt], qf[ks], &kb[cur][nt >> 1][(nt & 1) * 2]);
            }
        }

        // ---- mask + online softmax ----
        float tm0 = -1e30f, tm1 = -1e30f;
        #pragma unroll
        for (int nt = 0; nt < 8; nt++) {
            float ma  = mb[nt * 8 + 2 * t4];
            float mb2 = mb[nt * 8 + 2 * t4 + 1];
            sacc[nt][0] += ma; sacc[nt][1] += mb2;
            sacc[nt][2] += ma; sacc[nt][3] += mb2;
            tm0 = fmaxf(tm0, fmaxf(sacc[nt][0], sacc[nt][1]));
            tm1 = fmaxf(tm1, fmaxf(sacc[nt][2], sacc[nt][3]));
        }
        tm0 = fmaxf(tm0, __shfl_xor_sync(0xffffffff, tm0, 1));
        tm0 = fmaxf(tm0, __shfl_xor_sync(0xffffffff, tm0, 2));
        tm1 = fmaxf(tm1, __shfl_xor_sync(0xffffffff, tm1, 1));
        tm1 = fmaxf(tm1, __shfl_xor_sync(0xffffffff, tm1, 2));

        float mn0 = fmaxf(m0v, tm0);
        float mn1 = fmaxf(m1v, tm1);
        float f0 = __expf(m0v - mn0);
        float f1 = __expf(m1v - mn1);
        m0v = mn0; m1v = mn1;
        l0 *= f0; l1 *= f1;
        #pragma unroll
        for (int nt = 0; nt < 8; nt++) {
            oacc[nt][0] *= f0; oacc[nt][1] *= f0;
            oacc[nt][2] *= f1; oacc[nt][3] *= f1;
        }

        int r0 = warp * 16 + g;
        float s0 = 0.f, s1 = 0.f;
        #pragma unroll
        for (int nt = 0; nt < 8; nt++) {
            float e0 = __expf(sacc[nt][0] - mn0);
            float e1 = __expf(sacc[nt][1] - mn0);
            float e2 = __expf(sacc[nt][2] - mn1);
            float e3 = __expf(sacc[nt][3] - mn1);
            s0 += e0 + e1;
            s1 += e2 + e3;
            Ps[(r0)     * LDF + nt * 4 + t4] = f2h2(e0, e1);
            Ps[(r0 + 8) * LDF + nt * 4 + t4] = f2h2(e2, e3);
        }
        s0 += __shfl_xor_sync(0xffffffff, s0, 1);
        s0 += __shfl_xor_sync(0xffffffff, s0, 2);
        s1 += __shfl_xor_sync(0xffffffff, s1, 1);
        s1 += __shfl_xor_sync(0xffffffff, s1, 2);
        l0 += s0; l1 += s1;

        __syncwarp();   // P pane is warp-private

        // ---- O += P @ V  (P/V fragments double-buffered across ks) ----
        {
            uint32_t vb[2][4][4], af[2][4];
            ldsm4(af[0], sPs + (uint32_t)(rowAo * LDF + colAo) * 4);
            #pragma unroll
            for (int nt2 = 0; nt2 < 4; nt2++)
                ldsm4(vb[0][nt2], bV + (uint32_t)((rowB4 + nt2 * 16) * LDF + colB4) * 4);

            #pragma unroll
            for (int ks = 0; ks < 4; ks++) {
                const int cur = ks & 1;
                if (ks < 3) {
                    const int kk2n = (ks + 1) * 8;
                    ldsm4(af[cur ^ 1], sPs + (uint32_t)(rowAo * LDF + kk2n + colAo) * 4);
                    #pragma unroll
                    for (int nt2 = 0; nt2 < 4; nt2++)
                        ldsm4(vb[cur ^ 1][nt2],
                              bV + (uint32_t)((rowB4 + nt2 * 16) * LDF + kk2n + colB4) * 4);
                }
                #pragma unroll
                for (int nt = 0; nt < 8; nt++)
                    mma_f16(oacc[nt], af[cur], &vb[cur][nt >> 1][(nt & 1) * 2]);
            }
        }

        buf++; if (buf >= FST) buf = 0;
    }

    // ---- epilogue: normalize, write g_att (half2) ----
    {
        float inv0 = 1.f / l0;
        float inv1 = 1.f / l1;
        int r0 = q0 + warp * 16 + g;
        size_t base0 = ((size_t)(b * SEQ + r0))     * (CDIM / 2) + h * (HD / 2);
        size_t base1 = ((size_t)(b * SEQ + r0 + 8)) * (CDIM / 2) + h * (HD / 2);
        #pragma unroll
        for (int nt = 0; nt < 8; nt++) {
            g_att[base0 + nt * 4 + t4] = f2h2(oacc[nt][0] * inv0, oacc[nt][1] * inv0);
            g_att[base1 + nt * 4 + t4] = f2h2(oacc[nt][2] * inv1, oacc[nt][3] * inv1);
        }
    }
}

// ---------------------------------------------------------------------------
extern "C" void kernel_launch(void* const* d_in, const int* in_sizes, int n_in,
                              void* d_out, int out_size)
{
    const float* x      = (const float*)d_in[0];
    const int*   amask  = (const int*)  d_in[1];
    const float* W_attn = (const float*)d_in[2];
    const float* b_attn = (const float*)d_in[3];
    const float* W_proj = (const float*)d_in[4];
    const float* b_proj = (const float*)d_in[5];
    float* out = (float*)d_out;

    // 0) preconvert x -> half; transpose weights -> [N][K] half
    preconvert_x<<<(XN4 + 255) / 256, 256>>>(x);
    {
        dim3 g1(N3 / 32, CDIM / 32);
        transpose_w<0, CDIM, N3><<<g1, dim3(32, 8)>>>(W_attn);
        dim3 g2(CDIM / 32, CDIM / 32);
        transpose_w<1, CDIM, CDIM><<<g2, dim3(32, 8)>>>(W_proj);
    }

    const int gemm_smem = 2 * GST * TW * (int)sizeof(uint32_t);   // GST x (A+B)

    // 1) QKV GEMM (fp16 mma + ldmatrix, 3-stage, frag-pipelined) -> half q/k/vT
    {
        cudaFuncSetAttribute(gemm_h<1, CDIM, N3>,
                             cudaFuncAttributeMaxDynamicSharedMemorySize, gemm_smem);
        dim3 grid(N3 / 128, (BATCH * SEQ) / 128);
        gemm_h<1, CDIM, N3><<<grid, 256, gemm_smem>>>(b_attn, nullptr);
    }

    // 2) flash attention (fp16 mma + ldmatrix, 3-stage, frag-pipelined) -> half g_att
    {
        int smem = (2 * FST * KVW + BQT * LDF + FST * 64 + 64) * (int)sizeof(uint32_t);
        cudaFuncSetAttribute(flash_attn, cudaFuncAttributeMaxDynamicSharedMemorySize, smem);
        dim3 grid(SEQ / BQT, NH, BATCH);
        flash_attn<<<grid, 256, smem>>>(amask);
    }

    // 3) proj GEMM (fp16 mma + ldmatrix, 3-stage, frag-pipelined) -> fp32 out
    {
        cudaFuncSetAttribute(gemm_h<0, CDIM, CDIM>,
                             cudaFuncAttributeMaxDynamicSharedMemorySize, gemm_smem);
        dim3 grid(CDIM / 128, (BATCH * SEQ) / 128);
        gemm_h<0, CDIM, CDIM><<<grid, 256, gemm_smem>>>(b_proj, out);
    }
}